// round 2
// baseline (speedup 1.0000x reference)
#include <cuda_runtime.h>
#include <math.h>

#define B_  256
#define T_  512
#define IN_ 19
#define H_  512
#define G4  2048

// ---------------- static device scratch (no allocs allowed) ----------------
__device__ float g_h1all[T_][B_][H_];          // layer-1 outputs, [t][b][h]
__device__ float g_Bp1[16][17][32][128];       // packed layer-1 weights (K padded to 544)
__device__ float g_Bp2[16][32][32][128];       // packed layer-2 weights (K = 1024 = h1|h2)
__device__ float g_bias1[G4];
__device__ float g_bias2[G4];
__device__ float g_h1[2][B_][H_];              // ping-pong hidden state, layer 1
__device__ float g_c1[B_][H_];
__device__ float g_h2[2][B_][H_];
__device__ float g_c2[B_][H_];
__device__ unsigned g_bar;                     // software grid barrier counter

__device__ __forceinline__ float sigm_(float x) { return 1.0f / (1.0f + __expf(-x)); }

// ---------------- prep: pack weights, combine biases, zero states ----------
__global__ void __launch_bounds__(256) prep_kernel(
    const float* __restrict__ l1_Wx, const float* __restrict__ l1_bx,
    const float* __restrict__ l1_Wh, const float* __restrict__ l1_bh,
    const float* __restrict__ l2_Wx, const float* __restrict__ l2_bx,
    const float* __restrict__ l2_Wh, const float* __restrict__ l2_bh)
{
    int idx = blockIdx.x * blockDim.x + threadIdx.x;
    int stride = gridDim.x * blockDim.x;

    if (idx == 0) g_bar = 0u;   // reset barrier each replay

    for (int i = idx; i < G4; i += stride) {
        g_bias1[i] = l1_bx[i] + l1_bh[i];
        g_bias2[i] = l2_bx[i] + l2_bh[i];
    }
    for (int i = idx; i < B_ * H_; i += stride) {
        ((float*)g_h1)[i] = 0.0f;   // parity 0
        ((float*)g_c1)[i] = 0.0f;
        ((float*)g_h2)[i] = 0.0f;   // parity 0
        ((float*)g_c2)[i] = 0.0f;
    }
    // pack layer 1: K layout = [0,19): Wx, [19,32): zero, [32,544): Wh
    const int n1 = 16 * 17 * 32 * 128;
    for (int i = idx; i < n1; i += stride) {
        int nn = i & 127;
        int kk = (i >> 7) & 31;
        int kt = (i >> 12) % 17;
        int jb = (i >> 12) / 17;
        int gate = nn >> 5, jj = nn & 31;
        int row = gate * H_ + jb * 32 + jj;
        int k = kt * 32 + kk;
        float v = 0.0f;
        if (k < IN_)       v = l1_Wx[row * IN_ + k];
        else if (k >= 32)  v = l1_Wh[row * H_ + (k - 32)];
        ((float*)g_Bp1)[i] = v;
    }
    // pack layer 2: K layout = [0,512): Wx (applied to h1[t]), [512,1024): Wh
    const int n2 = 16 * 32 * 32 * 128;
    for (int i = idx; i < n2; i += stride) {
        int nn = i & 127;
        int kk = (i >> 7) & 31;
        int kt = (i >> 12) & 31;
        int jb = i >> 17;
        int gate = nn >> 5, jj = nn & 31;
        int row = gate * H_ + jb * 32 + jj;
        int k = kt * 32 + kk;
        float v = (k < H_) ? l2_Wx[row * H_ + k] : l2_Wh[row * H_ + (k - H_)];
        ((float*)g_Bp2)[i] = v;
    }
}

// ---------------- one fused LSTM step for one (jb,mb) tile ------------------
// Block tile: 32 batches (mb) x 32 hidden-j (jb) x 4 gates; each thread owns
// (4 rows) x (1 j) x (all 4 gates) -> cell update is fully thread-local.
template <int LAYER>
__device__ __forceinline__ void lstm_step_tile(
    const float* __restrict__ input, int t, int par, int jb, int mb,
    float (*A_s)[32], float (*B_s)[128])
{
    const int tid = threadIdx.x;
    const int tx = tid & 31;
    const int ty = tid >> 5;

    float acc[4][4] = {};

    const int KT = (LAYER == 1) ? 17 : 32;
    const float* __restrict__ Bp    = (LAYER == 1) ? &g_Bp1[jb][0][0][0] : &g_Bp2[jb][0][0][0];
    const float* __restrict__ hprev = (LAYER == 1) ? &g_h1[par][0][0]    : &g_h2[par][0][0];

    const int m_load = tid & 31;      // batch row this thread loads
    const int kg     = tid >> 5;      // k-subgroup 0..7 (4 k's each)
    const int m_g    = mb * 32 + m_load;

    for (int kt = 0; kt < KT; kt++) {
        // ---- A tile ----
        float4 av;
        if (LAYER == 1) {
            if (kt == 0) {
                float tmp[4];
                #pragma unroll
                for (int i = 0; i < 4; i++) {
                    int k = kg * 4 + i;
                    tmp[i] = (k < IN_) ? input[(size_t)m_g * (T_ * IN_) + t * IN_ + k] : 0.0f;
                }
                av = make_float4(tmp[0], tmp[1], tmp[2], tmp[3]);
            } else {
                int koff = kt * 32 - 32 + kg * 4;
                av = *(const float4*)&hprev[m_g * H_ + koff];
            }
        } else {
            int k = kt * 32 + kg * 4;
            const float* src = (k < H_) ? &g_h1all[t][m_g][k]
                                        : &hprev[m_g * H_ + (k - H_)];
            av = *(const float4*)src;
        }
        A_s[kg * 4 + 0][m_load] = av.x;
        A_s[kg * 4 + 1][m_load] = av.y;
        A_s[kg * 4 + 2][m_load] = av.z;
        A_s[kg * 4 + 3][m_load] = av.w;

        // ---- B tile: contiguous 4096-float copy ----
        const float4* bsrc = (const float4*)(Bp + (size_t)kt * 4096);
        float4* bdst = (float4*)&B_s[0][0];
        #pragma unroll
        for (int i = 0; i < 4; i++) bdst[tid + i * 256] = bsrc[tid + i * 256];

        __syncthreads();

        #pragma unroll 8
        for (int kk = 0; kk < 32; kk++) {
            float4 a = *(const float4*)&A_s[kk][ty * 4];
            float b0 = B_s[kk][tx];
            float b1 = B_s[kk][tx + 32];
            float b2 = B_s[kk][tx + 64];
            float b3 = B_s[kk][tx + 96];
            acc[0][0] += a.x * b0; acc[0][1] += a.x * b1; acc[0][2] += a.x * b2; acc[0][3] += a.x * b3;
            acc[1][0] += a.y * b0; acc[1][1] += a.y * b1; acc[1][2] += a.y * b2; acc[1][3] += a.y * b3;
            acc[2][0] += a.z * b0; acc[2][1] += a.z * b1; acc[2][2] += a.z * b2; acc[2][3] += a.z * b3;
            acc[3][0] += a.w * b0; acc[3][1] += a.w * b1; acc[3][2] += a.w * b2; acc[3][3] += a.w * b3;
        }
        __syncthreads();
    }

    // ---- fused LSTM cell update (thread-local: owns all 4 gates) ----
    const float* __restrict__ bias = (LAYER == 1) ? g_bias1 : g_bias2;
    float* __restrict__ C    = (LAYER == 1) ? &g_c1[0][0] : &g_c2[0][0];
    float* __restrict__ Hout = (LAYER == 1) ? &g_h1[par ^ 1][0][0] : &g_h2[par ^ 1][0][0];

    const int j = jb * 32 + tx;
    #pragma unroll
    for (int i = 0; i < 4; i++) {
        int m = mb * 32 + ty * 4 + i;
        float pi = acc[i][0] + bias[j];
        float pf = acc[i][1] + bias[H_ + j];
        float pg = acc[i][2] + bias[2 * H_ + j];
        float po = acc[i][3] + bias[3 * H_ + j];
        float c = C[m * H_ + j];
        c = sigm_(pf) * c + sigm_(pi) * tanhf(pg);
        float h = sigm_(po) * tanhf(c);
        C[m * H_ + j] = c;
        Hout[m * H_ + j] = h;
        if (LAYER == 1) g_h1all[t][m][j] = h;
    }
}

// ---------------- persistent kernel: both layers, software-pipelined --------
// Grid = 256 blocks, all co-resident (20KB smem, launch_bounds(256,2) ->
// 2 blocks/SM cap, 148 SMs * 2 = 296 slots >= 256). Blocks 0..127 compute
// layer 1 at step s; blocks 128..255 compute layer 2 at step s-1. A software
// grid barrier separates pipeline stages.
__global__ void __launch_bounds__(256, 2) lstm_persist(const float* __restrict__ input)
{
    __shared__ float A_s[32][32];
    __shared__ float B_s[32][128];

    const int group = blockIdx.x >> 7;          // 0: layer1, 1: layer2
    const int idx   = blockIdx.x & 127;
    const int jb    = idx & 15;
    const int mb    = idx >> 4;

    unsigned target = 0;

    for (int s = 0; s <= T_; s++) {
        if (group == 0) {
            if (s < T_) lstm_step_tile<1>(input, s, s & 1, jb, mb, A_s, B_s);
        } else {
            if (s >= 1) lstm_step_tile<2>(input, s - 1, (s - 1) & 1, jb, mb, A_s, B_s);
        }
        // ---- grid barrier ----
        target += 256;
        __syncthreads();
        if (threadIdx.x == 0) {
            __threadfence();
            atomicAdd(&g_bar, 1u);
            while (*(volatile unsigned*)&g_bar < target) { }
            __threadfence();
        }
        __syncthreads();
    }
}

// ---------------- FC head: one block per batch row --------------------------
__global__ void __launch_bounds__(256) fc_head(
    const float* __restrict__ fc1_W, const float* __restrict__ fc1_b,
    const float* __restrict__ fc2_W, const float* __restrict__ fc2_b,
    const float* __restrict__ fc3_W, const float* __restrict__ fc3_b,
    float* __restrict__ out)
{
    __shared__ float hv[512];
    __shared__ float o1[256];
    __shared__ float o2[128];
    const int b = blockIdx.x;
    const int tid = threadIdx.x;

    const float* h2 = &g_h2[0][b][0];   // final h2 lands in parity 0 after t=511
    hv[tid] = h2[tid];
    hv[tid + 256] = h2[tid + 256];
    __syncthreads();

    {
        float s = 0.0f;
        const float* w = &fc1_W[tid * 512];
        #pragma unroll 8
        for (int k = 0; k < 512; k++) s += w[k] * hv[k];
        o1[tid] = fmaxf(s + fc1_b[tid], 0.0f);
    }
    __syncthreads();

    if (tid < 128) {
        float s = 0.0f;
        const float* w = &fc2_W[tid * 256];
        #pragma unroll 8
        for (int k = 0; k < 256; k++) s += w[k] * o1[k];
        o2[tid] = fmaxf(s + fc2_b[tid], 0.0f);
    }
    __syncthreads();

    if (tid < 32) {
        float s = 0.0f;
        for (int k = tid; k < 128; k += 32) s += fc3_W[k] * o2[k];
        #pragma unroll
        for (int off = 16; off; off >>= 1) s += __shfl_down_sync(0xffffffffu, s, off);
        if (tid == 0) out[b] = s + fc3_b[0];
    }
}

// ---------------- launch -----------------------------------------------------
extern "C" void kernel_launch(void* const* d_in, const int* in_sizes, int n_in,
                              void* d_out, int out_size)
{
    const float* input  = (const float*)d_in[0];
    const float* l1_Wx  = (const float*)d_in[1];
    const float* l1_bx  = (const float*)d_in[2];
    const float* l1_Wh  = (const float*)d_in[3];
    const float* l1_bh  = (const float*)d_in[4];
    const float* l2_Wx  = (const float*)d_in[5];
    const float* l2_bx  = (const float*)d_in[6];
    const float* l2_Wh  = (const float*)d_in[7];
    const float* l2_bh  = (const float*)d_in[8];
    const float* fc1_W  = (const float*)d_in[9];
    const float* fc1_b  = (const float*)d_in[10];
    const float* fc2_W  = (const float*)d_in[11];
    const float* fc2_b  = (const float*)d_in[12];
    const float* fc3_W  = (const float*)d_in[13];
    const float* fc3_b  = (const float*)d_in[14];

    prep_kernel<<<512, 256>>>(l1_Wx, l1_bx, l1_Wh, l1_bh, l2_Wx, l2_bx, l2_Wh, l2_bh);
    lstm_persist<<<256, 256>>>(input);
    fc_head<<<256, 256>>>(fc1_W, fc1_b, fc2_W, fc2_b, fc3_W, fc3_b, (float*)d_out);
}

// round 3
// speedup vs baseline: 1.1741x; 1.1741x over previous
#include <cuda_runtime.h>
#include <math.h>

#define B_  256
#define T_  512
#define IN_ 19
#define H_  512
#define G4  2048

// ---------------- static device scratch (no allocs allowed) ----------------
__device__ float g_h1all[T_][B_][H_];          // layer-1 outputs, [t][b][h]
__device__ float g_Bp1[16][17][32][128];       // packed layer-1 weights (K padded to 544)
__device__ float g_Bp2[16][32][32][128];       // packed layer-2 weights (K = 1024 = h1|h2)
__device__ float g_bias1[G4];
__device__ float g_bias2[G4];
__device__ float g_h1[2][B_][H_];              // ping-pong hidden state, layer 1
__device__ float g_c1[B_][H_];
__device__ float g_h2[2][B_][H_];
__device__ float g_c2[B_][H_];
__device__ unsigned g_bar;                     // software grid barrier counter

__device__ __forceinline__ float sigm_(float x) { return 1.0f / (1.0f + __expf(-x)); }

// ---- packed fp32x2 helpers (Blackwell FFMA2 path: 2x fp32 FMA rate) -------
__device__ __forceinline__ unsigned long long pk2_(float x) {
    unsigned long long r;
    asm("mov.b64 %0, {%1, %1};" : "=l"(r) : "f"(x));
    return r;
}
__device__ __forceinline__ void fma2_(unsigned long long& d, unsigned long long a, unsigned long long b) {
    asm("fma.rn.f32x2 %0, %1, %2, %0;" : "+l"(d) : "l"(a), "l"(b));
}
__device__ __forceinline__ float2 up2_(unsigned long long v) {
    float2 f;
    asm("mov.b64 {%0, %1}, %2;" : "=f"(f.x), "=f"(f.y) : "l"(v));
    return f;
}

// ---------------- prep: pack weights, combine biases, zero states ----------
__global__ void __launch_bounds__(256) prep_kernel(
    const float* __restrict__ l1_Wx, const float* __restrict__ l1_bx,
    const float* __restrict__ l1_Wh, const float* __restrict__ l1_bh,
    const float* __restrict__ l2_Wx, const float* __restrict__ l2_bx,
    const float* __restrict__ l2_Wh, const float* __restrict__ l2_bh)
{
    int idx = blockIdx.x * blockDim.x + threadIdx.x;
    int stride = gridDim.x * blockDim.x;

    if (idx == 0) g_bar = 0u;   // reset barrier each replay

    for (int i = idx; i < G4; i += stride) {
        g_bias1[i] = l1_bx[i] + l1_bh[i];
        g_bias2[i] = l2_bx[i] + l2_bh[i];
    }
    for (int i = idx; i < B_ * H_; i += stride) {
        ((float*)g_h1)[i] = 0.0f;   // parity 0
        ((float*)g_c1)[i] = 0.0f;
        ((float*)g_h2)[i] = 0.0f;   // parity 0
        ((float*)g_c2)[i] = 0.0f;
    }
    // pack layer 1: K layout = [0,19): Wx, [19,32): zero, [32,544): Wh
    const int n1 = 16 * 17 * 32 * 128;
    for (int i = idx; i < n1; i += stride) {
        int nn = i & 127;
        int kk = (i >> 7) & 31;
        int kt = (i >> 12) % 17;
        int jb = (i >> 12) / 17;
        int gate = nn >> 5, jj = nn & 31;
        int row = gate * H_ + jb * 32 + jj;
        int k = kt * 32 + kk;
        float v = 0.0f;
        if (k < IN_)       v = l1_Wx[row * IN_ + k];
        else if (k >= 32)  v = l1_Wh[row * H_ + (k - 32)];
        ((float*)g_Bp1)[i] = v;
    }
    // pack layer 2: K layout = [0,512): Wx (applied to h1[t]), [512,1024): Wh
    const int n2 = 16 * 32 * 32 * 128;
    for (int i = idx; i < n2; i += stride) {
        int nn = i & 127;
        int kk = (i >> 7) & 31;
        int kt = (i >> 12) & 31;
        int jb = i >> 17;
        int gate = nn >> 5, jj = nn & 31;
        int row = gate * H_ + jb * 32 + jj;
        int k = kt * 32 + kk;
        float v = (k < H_) ? l2_Wx[row * H_ + k] : l2_Wh[row * H_ + (k - H_)];
        ((float*)g_Bp2)[i] = v;
    }
}

// ---------------- global->register stage for one k-tile ---------------------
template <int LAYER>
__device__ __forceinline__ void load_stage(
    const float* __restrict__ input, int t, int kt,
    const float* __restrict__ hprev, const float* __restrict__ Bp,
    int m_g, float4& av, float4 breg[4])
{
    const int tid = threadIdx.x;
    const int kg = tid >> 5;

    if (LAYER == 1) {
        if (kt == 0) {
            float tmp[4];
            #pragma unroll
            for (int i = 0; i < 4; i++) {
                int k = kg * 4 + i;
                tmp[i] = (k < IN_) ? input[(size_t)m_g * (T_ * IN_) + t * IN_ + k] : 0.0f;
            }
            av = make_float4(tmp[0], tmp[1], tmp[2], tmp[3]);
        } else {
            int koff = kt * 32 - 32 + kg * 4;
            av = *(const float4*)&hprev[m_g * H_ + koff];
        }
    } else {
        int k = kt * 32 + kg * 4;
        const float* src = (k < H_) ? &g_h1all[t][m_g][k]
                                    : &hprev[m_g * H_ + (k - H_)];
        av = *(const float4*)src;
    }
    const float4* bsrc = (const float4*)(Bp + (size_t)kt * 4096);
    #pragma unroll
    for (int i = 0; i < 4; i++) breg[i] = bsrc[tid + i * 256];
}

// ---------------- one fused LSTM step for one (jb,mb) tile ------------------
// Block tile: 32 batches (mb) x 32 hidden-j (jb) x 4 gates; each thread owns
// (4 rows) x (1 j) x (all 4 gates). Rows are processed as f32x2 pairs so the
// inner loop runs on the packed FFMA2 pipe (2x fp32 rate). Register-staged
// prefetch of the next k-tile hides L2 latency behind the FFMA2 block.
template <int LAYER>
__device__ __forceinline__ void lstm_step_tile(
    const float* __restrict__ input, int t, int par, int jb, int mb,
    float (*A_s)[32], float (*B_s)[128])
{
    const int tid = threadIdx.x;
    const int tx = tid & 31;
    const int ty = tid >> 5;

    // acc pairs: accp[p][g] = rows (2p, 2p+1) of gate g
    unsigned long long accp[2][4] = {};

    const int KT = (LAYER == 1) ? 17 : 32;
    const float* __restrict__ Bp    = (LAYER == 1) ? &g_Bp1[jb][0][0][0] : &g_Bp2[jb][0][0][0];
    const float* __restrict__ hprev = (LAYER == 1) ? &g_h1[par][0][0]    : &g_h2[par][0][0];

    const int m_load = tid & 31;      // batch row this thread loads
    const int kg     = tid >> 5;      // k-subgroup 0..7 (4 k's each)
    const int m_g    = mb * 32 + m_load;

    float4 av;
    float4 breg[4];
    load_stage<LAYER>(input, t, 0, hprev, Bp, m_g, av, breg);

    for (int kt = 0; kt < KT; kt++) {
        // ---- commit staged registers to smem ----
        A_s[kg * 4 + 0][m_load] = av.x;
        A_s[kg * 4 + 1][m_load] = av.y;
        A_s[kg * 4 + 2][m_load] = av.z;
        A_s[kg * 4 + 3][m_load] = av.w;
        float4* bdst = (float4*)&B_s[0][0];
        #pragma unroll
        for (int i = 0; i < 4; i++) bdst[tid + i * 256] = breg[i];
        __syncthreads();

        // ---- prefetch next k-tile into registers (overlaps with FFMA2) ----
        if (kt + 1 < KT)
            load_stage<LAYER>(input, t, kt + 1, hprev, Bp, m_g, av, breg);

        // ---- packed fp32x2 inner product ----
        #pragma unroll 8
        for (int kk = 0; kk < 32; kk++) {
            const unsigned long long* ap =
                (const unsigned long long*)&A_s[kk][ty * 4];
            unsigned long long a01 = ap[0];
            unsigned long long a23 = ap[1];
            unsigned long long b0 = pk2_(B_s[kk][tx]);
            unsigned long long b1 = pk2_(B_s[kk][tx + 32]);
            unsigned long long b2 = pk2_(B_s[kk][tx + 64]);
            unsigned long long b3 = pk2_(B_s[kk][tx + 96]);
            fma2_(accp[0][0], a01, b0); fma2_(accp[0][1], a01, b1);
            fma2_(accp[0][2], a01, b2); fma2_(accp[0][3], a01, b3);
            fma2_(accp[1][0], a23, b0); fma2_(accp[1][1], a23, b1);
            fma2_(accp[1][2], a23, b2); fma2_(accp[1][3], a23, b3);
        }
        __syncthreads();
    }

    // ---- fused LSTM cell update (thread-local: owns all 4 gates) ----
    const float* __restrict__ bias = (LAYER == 1) ? g_bias1 : g_bias2;
    float* __restrict__ C    = (LAYER == 1) ? &g_c1[0][0] : &g_c2[0][0];
    float* __restrict__ Hout = (LAYER == 1) ? &g_h1[par ^ 1][0][0] : &g_h2[par ^ 1][0][0];

    const int j = jb * 32 + tx;
    const float bi = bias[j];
    const float bf = bias[H_ + j];
    const float bg = bias[2 * H_ + j];
    const float bo = bias[3 * H_ + j];
    #pragma unroll
    for (int p = 0; p < 2; p++) {
        float2 gi = up2_(accp[p][0]);
        float2 gf = up2_(accp[p][1]);
        float2 gg = up2_(accp[p][2]);
        float2 go = up2_(accp[p][3]);
        #pragma unroll
        for (int q = 0; q < 2; q++) {
            int m = mb * 32 + ty * 4 + p * 2 + q;
            float pi = (q ? gi.y : gi.x) + bi;
            float pf = (q ? gf.y : gf.x) + bf;
            float pg = (q ? gg.y : gg.x) + bg;
            float po = (q ? go.y : go.x) + bo;
            float c = C[m * H_ + j];
            c = sigm_(pf) * c + sigm_(pi) * tanhf(pg);
            float h = sigm_(po) * tanhf(c);
            C[m * H_ + j] = c;
            Hout[m * H_ + j] = h;
            if (LAYER == 1) g_h1all[t][m][j] = h;
        }
    }
}

// ---------------- persistent kernel: both layers per block ------------------
// 128 blocks, one per SM (no co-residency pairing hazard). Each block owns
// tile (mb, jb) of BOTH layers: per interval s it computes layer-1 step s,
// then layer-2 step s-1 (software-pipelined), giving every block a uniform
// 17+32 k-tile cost. One grid barrier per interval.
__global__ void __launch_bounds__(256, 1) lstm_persist(const float* __restrict__ input)
{
    __shared__ float A_s[32][32];
    __shared__ float B_s[32][128];

    const int jb = blockIdx.x & 15;
    const int mb = blockIdx.x >> 4;   // 0..7

    unsigned target = 0;

    for (int s = 0; s <= T_; s++) {
        if (s < T_) lstm_step_tile<1>(input, s, s & 1, jb, mb, A_s, B_s);
        if (s >= 1) lstm_step_tile<2>(input, s - 1, (s - 1) & 1, jb, mb, A_s, B_s);

        // ---- grid barrier ----
        target += 128;
        __syncthreads();
        if (threadIdx.x == 0) {
            __threadfence();
            atomicAdd(&g_bar, 1u);
            while (*(volatile unsigned*)&g_bar < target) { }
            __threadfence();
        }
        __syncthreads();
    }
}

// ---------------- FC head: one block per batch row --------------------------
__global__ void __launch_bounds__(256) fc_head(
    const float* __restrict__ fc1_W, const float* __restrict__ fc1_b,
    const float* __restrict__ fc2_W, const float* __restrict__ fc2_b,
    const float* __restrict__ fc3_W, const float* __restrict__ fc3_b,
    float* __restrict__ out)
{
    __shared__ float hv[512];
    __shared__ float o1[256];
    __shared__ float o2[128];
    const int b = blockIdx.x;
    const int tid = threadIdx.x;

    const float* h2 = &g_h2[0][b][0];   // final h2 lands in parity 0 after t=511
    hv[tid] = h2[tid];
    hv[tid + 256] = h2[tid + 256];
    __syncthreads();

    {
        float s = 0.0f;
        const float* w = &fc1_W[tid * 512];
        #pragma unroll 8
        for (int k = 0; k < 512; k++) s += w[k] * hv[k];
        o1[tid] = fmaxf(s + fc1_b[tid], 0.0f);
    }
    __syncthreads();

    if (tid < 128) {
        float s = 0.0f;
        const float* w = &fc2_W[tid * 256];
        #pragma unroll 8
        for (int k = 0; k < 256; k++) s += w[k] * o1[k];
        o2[tid] = fmaxf(s + fc2_b[tid], 0.0f);
    }
    __syncthreads();

    if (tid < 32) {
        float s = 0.0f;
        for (int k = tid; k < 128; k += 32) s += fc3_W[k] * o2[k];
        #pragma unroll
        for (int off = 16; off; off >>= 1) s += __shfl_down_sync(0xffffffffu, s, off);
        if (tid == 0) out[b] = s + fc3_b[0];
    }
}

// ---------------- launch -----------------------------------------------------
extern "C" void kernel_launch(void* const* d_in, const int* in_sizes, int n_in,
                              void* d_out, int out_size)
{
    const float* input  = (const float*)d_in[0];
    const float* l1_Wx  = (const float*)d_in[1];
    const float* l1_bx  = (const float*)d_in[2];
    const float* l1_Wh  = (const float*)d_in[3];
    const float* l1_bh  = (const float*)d_in[4];
    const float* l2_Wx  = (const float*)d_in[5];
    const float* l2_bx  = (const float*)d_in[6];
    const float* l2_Wh  = (const float*)d_in[7];
    const float* l2_bh  = (const float*)d_in[8];
    const float* fc1_W  = (const float*)d_in[9];
    const float* fc1_b  = (const float*)d_in[10];
    const float* fc2_W  = (const float*)d_in[11];
    const float* fc2_b  = (const float*)d_in[12];
    const float* fc3_W  = (const float*)d_in[13];
    const float* fc3_b  = (const float*)d_in[14];

    prep_kernel<<<512, 256>>>(l1_Wx, l1_bx, l1_Wh, l1_bh, l2_Wx, l2_bx, l2_Wh, l2_bh);
    lstm_persist<<<128, 256>>>(input);
    fc_head<<<256, 256>>>(fc1_W, fc1_b, fc2_W, fc2_b, fc3_W, fc3_b, (float*)d_out);
}

// round 4
// speedup vs baseline: 1.3650x; 1.1626x over previous
#include <cuda_runtime.h>
#include <math.h>

#define B_  256
#define T_  512
#define IN_ 19
#define H_  512

typedef unsigned long long ull;

// ---------------- static device scratch (no allocs allowed) ----------------
__device__ float g_h1all[T_][B_][H_];          // layer-1 outputs, [t][b][h]
__device__ float g_h1[2][B_][H_];              // ping-pong hidden, layer 1
__device__ float g_h2[2][B_][H_];              // ping-pong hidden, layer 2
__device__ volatile unsigned g_count;          // grid barrier: arrivals (self-resets)
__device__ volatile unsigned g_gen;            // grid barrier: generation

__device__ __forceinline__ float sigm_(float x) { return 1.0f / (1.0f + __expf(-x)); }

// ---- packed fp32x2 helpers (FFMA2: full-rate fp32 on Blackwell) ----------
__device__ __forceinline__ ull pk2_(float x) {
    ull r;
    asm("mov.b64 %0, {%1, %1};" : "=l"(r) : "f"(x));
    return r;
}
__device__ __forceinline__ void fma2_(ull& d, ull a, ull b) {
    asm("fma.rn.f32x2 %0, %1, %2, %0;" : "+l"(d) : "l"(a), "l"(b));
}
__device__ __forceinline__ float2 up2_(ull v) {
    float2 f;
    asm("mov.b64 {%0, %1}, %2;" : "=f"(f.x), "=f"(f.y) : "l"(v));
    return f;
}

// ---------------- smem layout (dynamic, 217344 B) ---------------------------
// ws1: [17][32][32]  layer-1 weights  (17408 floats)
// ws2: [32][32][32]  layer-2 weights  (32768 floats)
// As : [32][130]     A tile, padded   (4160 floats)
#define WS1_FLOATS (17 * 32 * 32)
#define WS2_FLOATS (32 * 32 * 32)
#define AS_PAD     130
#define AS_FLOATS  (32 * AS_PAD)
#define SMEM_FLOATS (WS1_FLOATS + WS2_FLOATS + AS_FLOATS)
#define SMEM_BYTES  (SMEM_FLOATS * 4)

// ---------------- grid barrier (self-resetting, ncu-replay-safe) ------------
__device__ __forceinline__ void gbar() {
    __syncthreads();
    if (threadIdx.x == 0) {
        __threadfence();
        unsigned gen = g_gen;
        if (atomicAdd((unsigned*)&g_count, 1u) == 127u) {
            g_count = 0;
            __threadfence();
            g_gen = gen + 1u;
        } else {
            while (g_gen == gen) { }
        }
        __threadfence();
    }
    __syncthreads();
}

// ---------------- A-tile global->register load ------------------------------
template <int L>
__device__ __forceinline__ void loadA(
    const float* __restrict__ input, int t, int par, int kt,
    int f, int rr, int mb, float4 areg[8])
{
    #pragma unroll
    for (int it = 0; it < 8; it++) {
        int r = rr + it * 16;
        int m = mb * 128 + r;
        if (L == 1) {
            if (kt == 0) {
                float v[4];
                #pragma unroll
                for (int q = 0; q < 4; q++) {
                    int k = f * 4 + q;
                    v[q] = (k < IN_) ? input[(size_t)m * (T_ * IN_) + t * IN_ + k] : 0.0f;
                }
                areg[it] = make_float4(v[0], v[1], v[2], v[3]);
            } else {
                areg[it] = *(const float4*)&g_h1[par][m][(kt - 1) * 32 + f * 4];
            }
        } else {
            if (kt < 16) areg[it] = *(const float4*)&g_h1all[t][m][kt * 32 + f * 4];
            else         areg[it] = *(const float4*)&g_h2[par][m][(kt - 16) * 32 + f * 4];
        }
    }
}

// ---------------- one layer step for this block's tile ----------------------
// Thread tile: 8 rows x 1 j x 4 gates. Weights smem-resident, c in registers.
template <int L>
__device__ __forceinline__ void layer_step(
    const float* __restrict__ input, int t, int par,
    const float* __restrict__ ws, float* __restrict__ As,
    int tid, int jx, int mg, int mb, int j,
    const float bias4[4], float c[8])
{
    const int KT = (L == 1) ? 17 : 32;
    const int f  = tid & 7;
    const int rr = tid >> 3;

    ull acc[4][4] = {};

    float4 areg[8];
    loadA<L>(input, t, par, 0, f, rr, mb, areg);

    for (int kt = 0; kt < KT; kt++) {
        __syncthreads();   // previous consumers done with As
        // ---- commit A(kt) to smem (transposed [k][m]) ----
        #pragma unroll
        for (int it = 0; it < 8; it++) {
            int r = rr + it * 16;
            As[(f * 4 + 0) * AS_PAD + r] = areg[it].x;
            As[(f * 4 + 1) * AS_PAD + r] = areg[it].y;
            As[(f * 4 + 2) * AS_PAD + r] = areg[it].z;
            As[(f * 4 + 3) * AS_PAD + r] = areg[it].w;
        }
        __syncthreads();   // As ready
        // ---- prefetch next k-tile (overlaps with FFMA2 below) ----
        if (kt + 1 < KT) loadA<L>(input, t, par, kt + 1, f, rr, mb, areg);

        // ---- inner product: balanced crossbar/FFMA2 ----
        const float* Wk = ws + kt * 1024;
        #pragma unroll 8
        for (int kk = 0; kk < 32; kk++) {
            const float* w = Wk + kk * 32;
            ull b0 = pk2_(w[jx]);
            ull b1 = pk2_(w[8 + jx]);
            ull b2 = pk2_(w[16 + jx]);
            ull b3 = pk2_(w[24 + jx]);
            const float* ar = As + kk * AS_PAD + mg * 8;
            #pragma unroll
            for (int p = 0; p < 4; p++) {
                ull a = *(const ull*)(ar + 2 * p);
                fma2_(acc[p][0], a, b0);
                fma2_(acc[p][1], a, b1);
                fma2_(acc[p][2], a, b2);
                fma2_(acc[p][3], a, b3);
            }
        }
    }

    // ---- fused cell update (c lives in registers) ----
    float* __restrict__ Hout = (L == 1) ? &g_h1[par ^ 1][0][0] : &g_h2[par ^ 1][0][0];
    #pragma unroll
    for (int p = 0; p < 4; p++) {
        float2 gi = up2_(acc[p][0]);
        float2 gf = up2_(acc[p][1]);
        float2 gg = up2_(acc[p][2]);
        float2 go = up2_(acc[p][3]);
        #pragma unroll
        for (int q = 0; q < 2; q++) {
            int r = 2 * p + q;
            int m = mb * 128 + mg * 8 + r;
            float pi = (q ? gi.y : gi.x) + bias4[0];
            float pf = (q ? gf.y : gf.x) + bias4[1];
            float pg = (q ? gg.y : gg.x) + bias4[2];
            float po = (q ? go.y : go.x) + bias4[3];
            float cc = sigm_(pf) * c[r] + sigm_(pi) * tanhf(pg);
            c[r] = cc;
            float h = sigm_(po) * tanhf(cc);
            Hout[m * H_ + j] = h;
            if (L == 1) g_h1all[t][m][j] = h;
        }
    }
}

// ---------------- persistent kernel -----------------------------------------
// 128 blocks x 128 threads, all co-resident (212 KB smem -> 1 block/SM).
// Block owns (mb, jb): mb in 0..1 (128 rows), jb in 0..63 (8 hidden cols).
// Per interval s: layer-1 step s, then layer-2 step s-1 (pipelined), then a
// grid barrier. Weights live in smem for the whole run; c in registers.
__global__ void __launch_bounds__(128, 1) lstm_persist(
    const float* __restrict__ input,
    const float* __restrict__ l1_Wx, const float* __restrict__ l1_bx,
    const float* __restrict__ l1_Wh, const float* __restrict__ l1_bh,
    const float* __restrict__ l2_Wx, const float* __restrict__ l2_bx,
    const float* __restrict__ l2_Wh, const float* __restrict__ l2_bh)
{
    extern __shared__ float smem[];
    float* ws1 = smem;
    float* ws2 = smem + WS1_FLOATS;
    float* As  = smem + WS1_FLOATS + WS2_FLOATS;

    const int tid = threadIdx.x;
    const int jb  = blockIdx.x & 63;
    const int mb  = blockIdx.x >> 6;        // 0..1
    const int jx  = tid & 7;
    const int mg  = tid >> 3;               // 0..15
    const int j   = jb * 8 + jx;

    // ---- prologue: fill weight smem for this block's j-slice ----
    for (int i = tid; i < WS1_FLOATS; i += 128) {
        int x  = i & 31;
        int kk = (i >> 5) & 31;
        int kt = i >> 10;
        int g  = x >> 3;
        int jj = jb * 8 + (x & 7);
        int row = g * H_ + jj;
        int k = kt * 32 + kk;
        float v = 0.0f;
        if (k < IN_)      v = l1_Wx[row * IN_ + k];
        else if (k >= 32) v = l1_Wh[row * H_ + (k - 32)];
        ws1[i] = v;
    }
    for (int i = tid; i < WS2_FLOATS; i += 128) {
        int x  = i & 31;
        int kk = (i >> 5) & 31;
        int kt = i >> 10;
        int g  = x >> 3;
        int jj = jb * 8 + (x & 7);
        int row = g * H_ + jj;
        int k = kt * 32 + kk;
        ws2[i] = (k < H_) ? l2_Wx[row * H_ + k] : l2_Wh[row * H_ + (k - H_)];
    }

    // biases (combined) into registers
    float b1[4], b2[4];
    #pragma unroll
    for (int g = 0; g < 4; g++) {
        b1[g] = l1_bx[g * H_ + j] + l1_bh[g * H_ + j];
        b2[g] = l2_bx[g * H_ + j] + l2_bh[g * H_ + j];
    }

    // zero parity-0 h state (re-zeroed every launch)
    {
        int gt = blockIdx.x * 128 + tid;
        float* h1p = &g_h1[0][0][0];
        float* h2p = &g_h2[0][0][0];
        for (int i = gt; i < B_ * H_; i += 128 * 128) { h1p[i] = 0.0f; h2p[i] = 0.0f; }
    }

    float c1[8] = {}, c2[8] = {};

    gbar();   // weights + zeroed state visible everywhere

    // ---- main recurrence ----
    for (int s = 0; s <= T_; s++) {
        if (s < T_) layer_step<1>(input, s, s & 1, ws1, As, tid, jx, mg, mb, j, b1, c1);
        if (s >= 1) layer_step<2>(input, s - 1, (s - 1) & 1, ws2, As, tid, jx, mg, mb, j, b2, c2);
        gbar();
    }
}

// ---------------- FC head: one block per batch row --------------------------
__global__ void __launch_bounds__(256) fc_head(
    const float* __restrict__ fc1_W, const float* __restrict__ fc1_b,
    const float* __restrict__ fc2_W, const float* __restrict__ fc2_b,
    const float* __restrict__ fc3_W, const float* __restrict__ fc3_b,
    float* __restrict__ out)
{
    __shared__ float hv[512];
    __shared__ float o1[256];
    __shared__ float o2[128];
    const int b = blockIdx.x;
    const int tid = threadIdx.x;

    const float* h2 = &g_h2[0][b][0];   // final h2 lands in parity 0 after t=511
    hv[tid] = h2[tid];
    hv[tid + 256] = h2[tid + 256];
    __syncthreads();

    {
        float s = 0.0f;
        const float* w = &fc1_W[tid * 512];
        #pragma unroll 8
        for (int k = 0; k < 512; k++) s += w[k] * hv[k];
        o1[tid] = fmaxf(s + fc1_b[tid], 0.0f);
    }
    __syncthreads();

    if (tid < 128) {
        float s = 0.0f;
        const float* w = &fc2_W[tid * 256];
        #pragma unroll 8
        for (int k = 0; k < 256; k++) s += w[k] * o1[k];
        o2[tid] = fmaxf(s + fc2_b[tid], 0.0f);
    }
    __syncthreads();

    if (tid < 32) {
        float s = 0.0f;
        for (int k = tid; k < 128; k += 32) s += fc3_W[k] * o2[k];
        #pragma unroll
        for (int off = 16; off; off >>= 1) s += __shfl_down_sync(0xffffffffu, s, off);
        if (tid == 0) out[b] = s + fc3_b[0];
    }
}

// ---------------- launch -----------------------------------------------------
extern "C" void kernel_launch(void* const* d_in, const int* in_sizes, int n_in,
                              void* d_out, int out_size)
{
    const float* input  = (const float*)d_in[0];
    const float* l1_Wx  = (const float*)d_in[1];
    const float* l1_bx  = (const float*)d_in[2];
    const float* l1_Wh  = (const float*)d_in[3];
    const float* l1_bh  = (const float*)d_in[4];
    const float* l2_Wx  = (const float*)d_in[5];
    const float* l2_bx  = (const float*)d_in[6];
    const float* l2_Wh  = (const float*)d_in[7];
    const float* l2_bh  = (const float*)d_in[8];
    const float* fc1_W  = (const float*)d_in[9];
    const float* fc1_b  = (const float*)d_in[10];
    const float* fc2_W  = (const float*)d_in[11];
    const float* fc2_b  = (const float*)d_in[12];
    const float* fc3_W  = (const float*)d_in[13];
    const float* fc3_b  = (const float*)d_in[14];

    cudaFuncSetAttribute(lstm_persist,
                         cudaFuncAttributeMaxDynamicSharedMemorySize, SMEM_BYTES);

    lstm_persist<<<128, 128, SMEM_BYTES>>>(input,
        l1_Wx, l1_bx, l1_Wh, l1_bh, l2_Wx, l2_bx, l2_Wh, l2_bh);
    fc_head<<<256, 256>>>(fc1_W, fc1_b, fc2_W, fc2_b, fc3_W, fc3_b, (float*)d_out);
}

// round 7
// speedup vs baseline: 3.1188x; 2.2848x over previous
#include <cuda_runtime.h>
#include <cuda_bf16.h>
#include <math.h>
#include <stdint.h>

#define B_   256
#define T_   512
#define IN_  19
#define H_   512
#define KT1  9         // layer-1 chunks: 1 input + 8 hidden
#define KT2  16        // layer-2 chunks: 8 h1 + 8 h2
#define IMG  8192      // 64x64 bf16 swizzled image bytes (64 rows x 128B)
#define NCTA 128
#define BUFSZ 32768    // per-chunk smem: A_hi 8K | A_lo 8K | B_hi 8K | B_lo 8K
#define SMEM_DYN (120 * 1024)   // 3 x 32KB buffers; padded so only 1 CTA/SM fits

// ---------------- static device scratch (no allocs allowed) ----------------
__device__ __align__(16) unsigned char g_Bim1[32][KT1][2][IMG];    // [jb][chunk][hi/lo]
__device__ __align__(16) unsigned char g_Bim2[32][KT2][2][IMG];
__device__ __align__(16) unsigned char g_Ain[T_][4][2][IMG];       // [t][mh][hi/lo]
__device__ __align__(16) unsigned char g_h1im[2][4][8][2][IMG];    // [slot][mh][jchunk][hi/lo]
__device__ __align__(16) unsigned char g_h2im[2][4][8][2][IMG];
__device__ float g_bias1[4 * H_], g_bias2[4 * H_];
__device__ float g_h2fin[B_][H_];
__device__ volatile unsigned g_count;
__device__ volatile unsigned g_gen;

// ---------------- helpers ---------------------------------------------------
__device__ __forceinline__ uint32_t swz_(uint32_t o) { return o ^ ((o >> 3) & 0x70); }
__device__ __forceinline__ void split_bf16_(float w, unsigned short& hs, unsigned short& ls) {
    __nv_bfloat16 h = __float2bfloat16(w);
    float r = w - __bfloat162float(h);
    __nv_bfloat16 l = __float2bfloat16(r);
    hs = __bfloat16_as_ushort(h);
    ls = __bfloat16_as_ushort(l);
}
__device__ __forceinline__ float sigm_(float x) { return 1.0f / (1.0f + __expf(-x)); }
__device__ __forceinline__ float tanh_(float x) { return 1.0f - 2.0f / (__expf(2.0f * x) + 1.0f); }

__device__ __forceinline__ uint32_t smem_u32_(const void* p) {
    uint32_t a;
    asm("{ .reg .u64 t; cvta.to.shared.u64 t, %1; cvt.u32.u64 %0, t; }" : "=r"(a) : "l"(p));
    return a;
}
__device__ __forceinline__ void ldsm4_(uint32_t* r, uint32_t a) {
    asm volatile("ldmatrix.sync.aligned.m8n8.x4.shared.b16 {%0,%1,%2,%3}, [%4];"
        : "=r"(r[0]), "=r"(r[1]), "=r"(r[2]), "=r"(r[3]) : "r"(a));
}
__device__ __forceinline__ void mma_(float* d, const uint32_t* a, const uint32_t* b) {
    asm volatile("mma.sync.aligned.m16n8k16.row.col.f32.bf16.bf16.f32 "
        "{%0,%1,%2,%3}, {%4,%5,%6,%7}, {%8,%9}, {%0,%1,%2,%3};"
        : "+f"(d[0]), "+f"(d[1]), "+f"(d[2]), "+f"(d[3])
        : "r"(a[0]), "r"(a[1]), "r"(a[2]), "r"(a[3]), "r"(b[0]), "r"(b[1]));
}
__device__ __forceinline__ void cpa_(uint32_t sa, const void* ga) {
    asm volatile("cp.async.cg.shared.global [%0], [%1], 16;" :: "r"(sa), "l"(ga));
}

// ---------------- prep: build swizzled bf16 hi/lo images --------------------
__global__ void __launch_bounds__(256) prep_kernel(
    const float* __restrict__ input,
    const float* __restrict__ l1_Wx, const float* __restrict__ l1_bx,
    const float* __restrict__ l1_Wh, const float* __restrict__ l1_bh,
    const float* __restrict__ l2_Wx, const float* __restrict__ l2_bx,
    const float* __restrict__ l2_Wh, const float* __restrict__ l2_bh)
{
    int idx = blockIdx.x * blockDim.x + threadIdx.x;
    int stride = gridDim.x * blockDim.x;

    if (idx == 0) { g_count = 0u; g_gen = 0u; }

    for (int i = idx; i < 4 * H_; i += stride) {
        g_bias1[i] = l1_bx[i] + l1_bh[i];
        g_bias2[i] = l2_bx[i] + l2_bh[i];
    }

    // zero h images slot 0 (initial state)
    {
        int n16 = (4 * 8 * 2 * IMG) / 16;
        uint4 z = make_uint4(0, 0, 0, 0);
        uint4* p1 = (uint4*)&g_h1im[0][0][0][0][0];
        uint4* p2 = (uint4*)&g_h2im[0][0][0][0][0];
        for (int i = idx; i < n16; i += stride) { p1[i] = z; p2[i] = z; }
    }

    // layer-1 B images: 32 jb x 9 chunks x 64 rows x 8 16B-groups
    for (int e = idx; e < 32 * KT1 * 64 * 8; e += stride) {
        int k8 = e & 7, nrow = (e >> 3) & 63, c = (e >> 9) % KT1, jb = (e >> 9) / KT1;
        int g = nrow >> 4, jj = nrow & 15;
        int R = g * H_ + jb * 16 + jj;
        unsigned u[4], v[4];
        #pragma unroll
        for (int q = 0; q < 4; q++) {
            unsigned short hs[2], ls[2];
            #pragma unroll
            for (int h = 0; h < 2; h++) {
                int k = k8 * 8 + q * 2 + h;
                float w;
                if (c == 0) w = (k < IN_) ? l1_Wx[R * IN_ + k] : 0.0f;
                else        w = l1_Wh[R * H_ + (c - 1) * 64 + k];
                split_bf16_(w, hs[h], ls[h]);
            }
            u[q] = (unsigned)hs[0] | ((unsigned)hs[1] << 16);
            v[q] = (unsigned)ls[0] | ((unsigned)ls[1] << 16);
        }
        uint32_t off = swz_((uint32_t)(nrow * 128 + k8 * 16));
        *(uint4*)&g_Bim1[jb][c][0][off] = make_uint4(u[0], u[1], u[2], u[3]);
        *(uint4*)&g_Bim1[jb][c][1][off] = make_uint4(v[0], v[1], v[2], v[3]);
    }

    // layer-2 B images: chunks 0-7 = Wx (vs h1), 8-15 = Wh (vs h2)
    for (int e = idx; e < 32 * KT2 * 64 * 8; e += stride) {
        int k8 = e & 7, nrow = (e >> 3) & 63, c = (e >> 9) & 15, jb = e >> 13;
        int g = nrow >> 4, jj = nrow & 15;
        int R = g * H_ + jb * 16 + jj;
        unsigned u[4], v[4];
        #pragma unroll
        for (int q = 0; q < 4; q++) {
            unsigned short hs[2], ls[2];
            #pragma unroll
            for (int h = 0; h < 2; h++) {
                int k = k8 * 8 + q * 2 + h;
                float w = (c < 8) ? l2_Wx[R * H_ + c * 64 + k]
                                  : l2_Wh[R * H_ + (c - 8) * 64 + k];
                split_bf16_(w, hs[h], ls[h]);
            }
            u[q] = (unsigned)hs[0] | ((unsigned)hs[1] << 16);
            v[q] = (unsigned)ls[0] | ((unsigned)ls[1] << 16);
        }
        uint32_t off = swz_((uint32_t)(nrow * 128 + k8 * 16));
        *(uint4*)&g_Bim2[jb][c][0][off] = make_uint4(u[0], u[1], u[2], u[3]);
        *(uint4*)&g_Bim2[jb][c][1][off] = make_uint4(v[0], v[1], v[2], v[3]);
    }

    // input A images: [t][mh 0..3], rows 0..63, cols 0..63 (19 real + pad)
    for (int e = idx; e < T_ * 4 * 64 * 8; e += stride) {
        int k8 = e & 7, r = (e >> 3) & 63, mh = (e >> 9) & 3, t = e >> 11;
        int b = mh * 64 + r;
        unsigned u[4], v[4];
        #pragma unroll
        for (int q = 0; q < 4; q++) {
            unsigned short hs[2], ls[2];
            #pragma unroll
            for (int h = 0; h < 2; h++) {
                int k = k8 * 8 + q * 2 + h;
                float w = (k < IN_) ? input[(size_t)b * (T_ * IN_) + t * IN_ + k] : 0.0f;
                split_bf16_(w, hs[h], ls[h]);
            }
            u[q] = (unsigned)hs[0] | ((unsigned)hs[1] << 16);
            v[q] = (unsigned)ls[0] | ((unsigned)ls[1] << 16);
        }
        uint32_t off = swz_((uint32_t)(r * 128 + k8 * 16));
        *(uint4*)&g_Ain[t][mh][0][off] = make_uint4(u[0], u[1], u[2], u[3]);
        *(uint4*)&g_Ain[t][mh][1][off] = make_uint4(v[0], v[1], v[2], v[3]);
    }
}

// ---------------- grid barrier (self-resetting) ------------------------------
__device__ __forceinline__ void gbar_() {
    __syncthreads();
    if (threadIdx.x == 0) {
        __threadfence();
        unsigned gen = g_gen;
        if (atomicAdd((unsigned*)&g_count, 1u) == NCTA - 1u) {
            g_count = 0;
            __threadfence();
            g_gen = gen + 1u;
        } else {
            while (g_gen == gen) { }
        }
        __threadfence();
    }
    __syncthreads();
}

// ---------------- chunk source resolution ------------------------------------
__device__ __forceinline__ void chunk_src_(int cc, int n1, int s, int mh, int jb,
    const uint4*& ah, const uint4*& al, const uint4*& bh, const uint4*& bl)
{
    if (cc < n1) {               // layer 1 at step s
        int c = cc;
        if (c == 0) { ah = (const uint4*)g_Ain[s][mh][0];            al = (const uint4*)g_Ain[s][mh][1]; }
        else        { ah = (const uint4*)g_h1im[s & 1][mh][c - 1][0]; al = (const uint4*)g_h1im[s & 1][mh][c - 1][1]; }
        bh = (const uint4*)g_Bim1[jb][c][0];
        bl = (const uint4*)g_Bim1[jb][c][1];
    } else {                     // layer 2 at step s-1
        int c = cc - n1;
        if (c < 8)  { ah = (const uint4*)g_h1im[s & 1][mh][c][0];           al = (const uint4*)g_h1im[s & 1][mh][c][1]; }
        else        { ah = (const uint4*)g_h2im[(s - 1) & 1][mh][c - 8][0]; al = (const uint4*)g_h2im[(s - 1) & 1][mh][c - 8][1]; }
        bh = (const uint4*)g_Bim2[jb][c][0];
        bl = (const uint4*)g_Bim2[jb][c][1];
    }
}

__device__ __forceinline__ void issue_chunk_(uint32_t sbuf,
    const uint4* ah, const uint4* al, const uint4* bh, const uint4* bl, int tid)
{
    #pragma unroll
    for (int i = 0; i < 4; i++) {
        int e = tid + i * 128;
        cpa_(sbuf + e * 16,          ah + e);
        cpa_(sbuf + 8192  + e * 16,  al + e);
        cpa_(sbuf + 16384 + e * 16,  bh + e);
        cpa_(sbuf + 24576 + e * 16,  bl + e);
    }
    asm volatile("cp.async.commit_group;" ::: "memory");
}

// ---------------- one chunk of MMA: 3-pass bf16 split ------------------------
__device__ __forceinline__ void compute_chunk_(uint32_t sbuf, float acc[8][4], int l, int w)
{
    const uint32_t arow  = (uint32_t)(w * 16 + (l & 15));
    const uint32_t abyte = (uint32_t)(((l >> 4) & 1) * 16);
    const uint32_t brow0 = (uint32_t)(((l >> 4) & 1) * 8 + (l & 7));
    const uint32_t bbyte = (uint32_t)(((l >> 3) & 1) * 16);

    #pragma unroll
    for (int ks = 0; ks < 4; ks++) {
        uint32_t ah[4], al4[4];
        uint32_t aoff = swz_(arow * 128 + (uint32_t)ks * 32 + abyte);
        ldsm4_(ah,  sbuf + aoff);
        ldsm4_(al4, sbuf + 8192 + aoff);
        #pragma unroll
        for (int tp = 0; tp < 4; tp++) {
            uint32_t boff = swz_(((uint32_t)tp * 16 + brow0) * 128 + (uint32_t)ks * 32 + bbyte);
            uint32_t bh4[4], bl4[4];
            ldsm4_(bh4, sbuf + 16384 + boff);
            ldsm4_(bl4, sbuf + 24576 + boff);
            mma_(acc[2 * tp],     ah,  bh4);
            mma_(acc[2 * tp + 1], ah,  bh4 + 2);
            mma_(acc[2 * tp],     ah,  bl4);
            mma_(acc[2 * tp + 1], ah,  bl4 + 2);
            mma_(acc[2 * tp],     al4, bh4);
            mma_(acc[2 * tp + 1], al4, bh4 + 2);
        }
    }
}

// ---------------- fused LSTM cell epilogue -----------------------------------
__device__ __forceinline__ void epilogue_(float acc[8][4], float* cst, const float* sb,
    int layer, int t, int mh, int jb, int w, int l, bool lastw)
{
    unsigned char* hb0 = (layer ? g_h2im : g_h1im)[(t + 1) & 1][mh][jb >> 2][0];
    unsigned char* hb1 = (layer ? g_h2im : g_h1im)[(t + 1) & 1][mh][jb >> 2][1];

    #pragma unroll
    for (int a = 0; a < 2; a++) {
        #pragma unroll
        for (int rh = 0; rh < 2; rh++) {
            int row = 16 * w + (l >> 2) + rh * 8;
            unsigned short hhi[2], hlo[2];
            #pragma unroll
            for (int b = 0; b < 2; b++) {
                int jj = 8 * a + 2 * (l & 3) + b;
                float pi = acc[a][rh * 2 + b]     + sb[jj];
                float pf = acc[a + 2][rh * 2 + b] + sb[16 + jj];
                float pg = acc[a + 4][rh * 2 + b] + sb[32 + jj];
                float po = acc[a + 6][rh * 2 + b] + sb[48 + jj];
                int ci = a * 4 + rh * 2 + b;
                float cc = sigm_(pf) * cst[ci] + sigm_(pi) * tanh_(pg);
                cst[ci] = cc;
                float h = sigm_(po) * tanh_(cc);
                split_bf16_(h, hhi[b], hlo[b]);
                if (lastw) g_h2fin[mh * 64 + row][jb * 16 + jj] = h;
            }
            uint32_t off = swz_((uint32_t)(row * 128 + ((jb & 3) * 16 + 8 * a + 2 * (l & 3)) * 2));
            *(uint32_t*)(hb0 + off) = (uint32_t)hhi[0] | ((uint32_t)hhi[1] << 16);
            *(uint32_t*)(hb1 + off) = (uint32_t)hlo[0] | ((uint32_t)hlo[1] << 16);
        }
    }
}

// ---------------- persistent warp-MMA LSTM -----------------------------------
// 128 CTAs x 128 threads, 1/SM (smem-forced). CTA (mh 0..3, jb 0..31) owns a
// 64-row x 16-j tile of BOTH layers: per interval s it streams 9 L1 chunks
// (step s) + 16 L2 chunks (step s-1) through a 3-buffer cp.async pipeline into
// m16n8k16 bf16 mma (3-pass split precision). One grid barrier per interval.
__global__ void __launch_bounds__(128, 1) lstm_persist()
{
    extern __shared__ unsigned char dsm[];
    __shared__ float s_bias[2][64];

    const int tid = threadIdx.x;
    const int l = tid & 31;
    const int w = tid >> 5;
    const int mh = blockIdx.x >> 5;       // 0..3
    const int jb = blockIdx.x & 31;       // 0..31

    const uint32_t bufu = smem_u32_(dsm);

    if (tid < 128) {
        int layer = tid >> 6, i = tid & 63;
        const float* bsrc = layer ? g_bias2 : g_bias1;
        s_bias[layer][i] = bsrc[(i >> 4) * H_ + jb * 16 + (i & 15)];
    }
    __syncthreads();

    float c1[8], c2[8];
    #pragma unroll
    for (int i = 0; i < 8; i++) { c1[i] = 0.0f; c2[i] = 0.0f; }

    for (int s = 0; s <= T_; s++) {
        const bool hasL1 = (s < T_), hasL2 = (s >= 1);
        const int n1 = hasL1 ? KT1 : 0;
        const int nch = n1 + (hasL2 ? KT2 : 0);

        // prologue: issue chunks 0,1
        {
            const uint4 *ah, *al, *bh, *bl;
            chunk_src_(0, n1, s, mh, jb, ah, al, bh, bl);
            issue_chunk_(bufu, ah, al, bh, bl, tid);
            chunk_src_(1, n1, s, mh, jb, ah, al, bh, bl);
            issue_chunk_(bufu + BUFSZ, ah, al, bh, bl, tid);
        }

        float acc[8][4];
        for (int cc = 0; cc < nch; cc++) {
            if (cc < nch - 1) asm volatile("cp.async.wait_group 1;" ::: "memory");
            else              asm volatile("cp.async.wait_group 0;" ::: "memory");
            __syncthreads();

            if (cc + 2 < nch) {
                const uint4 *ah, *al, *bh, *bl;
                chunk_src_(cc + 2, n1, s, mh, jb, ah, al, bh, bl);
                issue_chunk_(bufu + ((cc + 2) % 3) * BUFSZ, ah, al, bh, bl, tid);
            }

            if (cc == 0 || cc == n1) {
                #pragma unroll
                for (int nt = 0; nt < 8; nt++)
                    #pragma unroll
                    for (int r = 0; r < 4; r++) acc[nt][r] = 0.0f;
            }

            compute_chunk_(bufu + (cc % 3) * BUFSZ, acc, l, w);

            if (hasL1 && cc == n1 - 1)
                epilogue_(acc, c1, s_bias[0], 0, s, mh, jb, w, l, false);
            if (hasL2 && cc == nch - 1)
                epilogue_(acc, c2, s_bias[1], 1, s - 1, mh, jb, w, l, (s - 1) == T_ - 1);
        }
        gbar_();
    }
}

// ---------------- FC head: 32 blocks x 8 batches -----------------------------
__global__ void __launch_bounds__(256) fc_head(
    const float* __restrict__ fc1_W, const float* __restrict__ fc1_b,
    const float* __restrict__ fc2_W, const float* __restrict__ fc2_b,
    const float* __restrict__ fc3_W, const float* __restrict__ fc3_b,
    float* __restrict__ out)
{
    __shared__ float hv[8][512];
    __shared__ float o1s[8][256];
    __shared__ float o2s[8][128];
    const int tid = threadIdx.x;
    const int b0 = blockIdx.x * 8;

    for (int i = tid; i < 8 * 512; i += 256) hv[i >> 9][i & 511] = g_h2fin[b0 + (i >> 9)][i & 511];
    __syncthreads();

    {
        float acc[8] = {};
        const float* w = &fc1_W[tid * 512];
        for (int k = 0; k < 512; k++) {
            float wv = w[k];
            #pragma unroll
            for (int q = 0; q < 8; q++) acc[q] += wv * hv[q][k];
        }
        float b = fc1_b[tid];
        #pragma unroll
        for (int q = 0; q < 8; q++) o1s[q][tid] = fmaxf(acc[q] + b, 0.0f);
    }
    __syncthreads();

    if (tid < 128) {
        float acc[8] = {};
        const float* w = &fc2_W[tid * 256];
        for (int k = 0; k < 256; k++) {
            float wv = w[k];
            #pragma unroll
            for (int q = 0; q < 8; q++) acc[q] += wv * o1s[q][k];
        }
        float b = fc2_b[tid];
        #pragma unroll
        for (int q = 0; q < 8; q++) o2s[q][tid] = fmaxf(acc[q] + b, 0.0f);
    }
    __syncthreads();

    {
        int q = tid >> 5, lane = tid & 31;
        float s = 0.0f;
        for (int k = lane; k < 128; k += 32) s += fc3_W[k] * o2s[q][k];
        #pragma unroll
        for (int off = 16; off; off >>= 1) s += __shfl_down_sync(0xffffffffu, s, off);
        if (lane == 0) out[b0 + q] = s + fc3_b[0];
    }
}

__global__ void dummy_k() {}

// ---------------- launch -----------------------------------------------------
extern "C" void kernel_launch(void* const* d_in, const int* in_sizes, int n_in,
                              void* d_out, int out_size)
{
    const float* input  = (const float*)d_in[0];
    const float* l1_Wx  = (const float*)d_in[1];
    const float* l1_bx  = (const float*)d_in[2];
    const float* l1_Wh  = (const float*)d_in[3];
    const float* l1_bh  = (const float*)d_in[4];
    const float* l2_Wx  = (const float*)d_in[5];
    const float* l2_bx  = (const float*)d_in[6];
    const float* l2_Wh  = (const float*)d_in[7];
    const float* l2_bh  = (const float*)d_in[8];
    const float* fc1_W  = (const float*)d_in[9];
    const float* fc1_b  = (const float*)d_in[10];
    const float* fc2_W  = (const float*)d_in[11];
    const float* fc2_b  = (const float*)d_in[12];
    const float* fc3_W  = (const float*)d_in[13];
    const float* fc3_b  = (const float*)d_in[14];

    cudaFuncSetAttribute(lstm_persist,
                         cudaFuncAttributeMaxDynamicSharedMemorySize, SMEM_DYN);

    prep_kernel<<<2048, 256>>>(input, l1_Wx, l1_bx, l1_Wh, l1_bh,
                               l2_Wx, l2_bx, l2_Wh, l2_bh);
    lstm_persist<<<NCTA, 128, SMEM_DYN>>>();
    fc_head<<<32, 256>>>(fc1_W, fc1_b, fc2_W, fc2_b, fc3_W, fc3_b, (float*)d_out);
    dummy_k<<<1, 32>>>();   // aligns ncu -s 5 onto lstm_persist next replay
}

// round 8
// speedup vs baseline: 6.6399x; 2.1290x over previous
#include <cuda_runtime.h>
#include <cuda_fp16.h>
#include <math.h>
#include <stdint.h>

#define B_   256
#define T_   512
#define IN_  19
#define H_   512
#define KT1  9         // layer-1 chunks: 1 input + 8 hidden
#define KT2  16        // layer-2 chunks: 8 h1 + 8 h2
#define IMG  8192      // 64x64 fp16 swizzled image bytes (64 rows x 128B)
#define NCTA 128
#define BUFSZ 16384    // per-chunk smem: A 8K | B 8K
#define SMEM_DYN (120 * 1024)   // 3 x 16KB buffers + pad so only 1 CTA/SM fits

// ---------------- static device scratch (no allocs allowed) ----------------
__device__ __align__(16) unsigned char g_Bim1[32][KT1][IMG];   // [jb][chunk]
__device__ __align__(16) unsigned char g_Bim2[32][KT2][IMG];
__device__ __align__(16) unsigned char g_Ain[T_][4][IMG];      // [t][mh]
__device__ __align__(16) unsigned char g_h1im[2][4][8][IMG];   // [slot][mh][jchunk]
__device__ __align__(16) unsigned char g_h2im[2][4][8][IMG];
__device__ float g_bias1[4 * H_], g_bias2[4 * H_];
__device__ float g_h2fin[B_][H_];
__device__ volatile unsigned g_count;
__device__ volatile unsigned g_gen;

// ---------------- helpers ---------------------------------------------------
__device__ __forceinline__ uint32_t swz_(uint32_t o) { return o ^ ((o >> 3) & 0x70); }
__device__ __forceinline__ float tanha_(float x) {
    float y;
    asm("tanh.approx.f32 %0, %1;" : "=f"(y) : "f"(x));
    return y;
}
__device__ __forceinline__ float sigm_(float x) { return 0.5f * tanha_(0.5f * x) + 0.5f; }

__device__ __forceinline__ uint32_t smem_u32_(const void* p) {
    uint32_t a;
    asm("{ .reg .u64 t; cvta.to.shared.u64 t, %1; cvt.u32.u64 %0, t; }" : "=r"(a) : "l"(p));
    return a;
}
__device__ __forceinline__ void ldsm4_(uint32_t* r, uint32_t a) {
    asm volatile("ldmatrix.sync.aligned.m8n8.x4.shared.b16 {%0,%1,%2,%3}, [%4];"
        : "=r"(r[0]), "=r"(r[1]), "=r"(r[2]), "=r"(r[3]) : "r"(a));
}
__device__ __forceinline__ void mma_(float* d, const uint32_t* a, const uint32_t* b) {
    asm volatile("mma.sync.aligned.m16n8k16.row.col.f32.f16.f16.f32 "
        "{%0,%1,%2,%3}, {%4,%5,%6,%7}, {%8,%9}, {%0,%1,%2,%3};"
        : "+f"(d[0]), "+f"(d[1]), "+f"(d[2]), "+f"(d[3])
        : "r"(a[0]), "r"(a[1]), "r"(a[2]), "r"(a[3]), "r"(b[0]), "r"(b[1]));
}
__device__ __forceinline__ void cpa_(uint32_t sa, const void* ga) {
    asm volatile("cp.async.cg.shared.global [%0], [%1], 16;" :: "r"(sa), "l"(ga));
}
__device__ __forceinline__ uint32_t pk8_(const float* v, int n, uint32_t* out4) {
    // pack 8 floats -> 8 fp16 in 4 u32 (n = valid count, rest 0)
    #pragma unroll
    for (int q = 0; q < 4; q++) {
        unsigned short h0 = (2 * q     < n) ? __half_as_ushort(__float2half_rn(v[2 * q]))     : 0;
        unsigned short h1 = (2 * q + 1 < n) ? __half_as_ushort(__float2half_rn(v[2 * q + 1])) : 0;
        out4[q] = (uint32_t)h0 | ((uint32_t)h1 << 16);
    }
    return 0;
}

// ---------------- grid barrier (self-resetting, replay-safe) -----------------
__device__ __forceinline__ void gbar_() {
    __syncthreads();
    if (threadIdx.x == 0) {
        __threadfence();
        unsigned gen = g_gen;
        if (atomicAdd((unsigned*)&g_count, 1u) == NCTA - 1u) {
            g_count = 0;
            __threadfence();
            g_gen = gen + 1u;
        } else {
            while (g_gen == gen) { }
        }
        __threadfence();
    }
    __syncthreads();
}

// ---------------- chunk source resolution ------------------------------------
__device__ __forceinline__ void chunk_src_(int cc, int n1, int s, int mh, int jb,
    const uint4*& ah, const uint4*& bh)
{
    if (cc < n1) {               // layer 1 at step s
        int c = cc;
        if (c == 0) ah = (const uint4*)g_Ain[s][mh];
        else        ah = (const uint4*)g_h1im[s & 1][mh][c - 1];
        bh = (const uint4*)g_Bim1[jb][c];
    } else {                     // layer 2 at step s-1
        int c = cc - n1;
        if (c < 8)  ah = (const uint4*)g_h1im[s & 1][mh][c];
        else        ah = (const uint4*)g_h2im[(s - 1) & 1][mh][c - 8];
        bh = (const uint4*)g_Bim2[jb][c];
    }
}

__device__ __forceinline__ void issue_chunk_(uint32_t sbuf, const uint4* ah, const uint4* bh, int tid)
{
    #pragma unroll
    for (int i = 0; i < 4; i++) {
        int e = tid + i * 128;
        cpa_(sbuf + e * 16,        ah + e);
        cpa_(sbuf + 8192 + e * 16, bh + e);
    }
    asm volatile("cp.async.commit_group;" ::: "memory");
}

// ---------------- one chunk of MMA: single-pass fp16 -------------------------
__device__ __forceinline__ void compute_chunk_(uint32_t sbuf, float acc[8][4], int l, int w)
{
    const uint32_t arow  = (uint32_t)(w * 16 + (l & 15));
    const uint32_t abyte = (uint32_t)(((l >> 4) & 1) * 16);
    const uint32_t brow0 = (uint32_t)(((l >> 4) & 1) * 8 + (l & 7));
    const uint32_t bbyte = (uint32_t)(((l >> 3) & 1) * 16);

    #pragma unroll
    for (int ks = 0; ks < 4; ks++) {
        uint32_t a4[4];
        ldsm4_(a4, sbuf + swz_(arow * 128 + (uint32_t)ks * 32 + abyte));
        #pragma unroll
        for (int tp = 0; tp < 4; tp++) {
            uint32_t b4[4];
            ldsm4_(b4, sbuf + 8192 + swz_(((uint32_t)tp * 16 + brow0) * 128 + (uint32_t)ks * 32 + bbyte));
            mma_(acc[2 * tp],     a4, b4);
            mma_(acc[2 * tp + 1], a4, b4 + 2);
        }
    }
}

// ---------------- fused LSTM cell epilogue -----------------------------------
__device__ __forceinline__ void epilogue_(float acc[8][4], float* cst, const float* sb,
    int layer, int t, int mh, int jb, int w, int l, bool lastw)
{
    unsigned char* hb0 = (layer ? g_h2im : g_h1im)[(t + 1) & 1][mh][jb >> 2];

    #pragma unroll
    for (int a = 0; a < 2; a++) {
        #pragma unroll
        for (int rh = 0; rh < 2; rh++) {
            int row = 16 * w + (l >> 2) + rh * 8;
            unsigned short hf[2];
            #pragma unroll
            for (int b = 0; b < 2; b++) {
                int jj = 8 * a + 2 * (l & 3) + b;
                float pi = acc[a][rh * 2 + b]     + sb[jj];
                float pf = acc[a + 2][rh * 2 + b] + sb[16 + jj];
                float pg = acc[a + 4][rh * 2 + b] + sb[32 + jj];
                float po = acc[a + 6][rh * 2 + b] + sb[48 + jj];
                int ci = a * 4 + rh * 2 + b;
                float cc = sigm_(pf) * cst[ci] + sigm_(pi) * tanha_(pg);
                cst[ci] = cc;
                float h = sigm_(po) * tanha_(cc);
                hf[b] = __half_as_ushort(__float2half_rn(h));
                if (lastw) g_h2fin[mh * 64 + row][jb * 16 + jj] = h;
            }
            uint32_t off = swz_((uint32_t)(row * 128 + ((jb & 3) * 16 + 8 * a + 2 * (l & 3)) * 2));
            *(uint32_t*)(hb0 + off) = (uint32_t)hf[0] | ((uint32_t)hf[1] << 16);
        }
    }
}

// ---------------- THE kernel: prep + persistent LSTM + FC head ---------------
// 128 CTAs x 128 threads, 1/SM (smem-forced). CTA (mh 0..3, jb 0..31) owns a
// 64-row x 16-j tile of BOTH layers; per interval s: 9 L1 chunks (step s) +
// 16 L2 chunks (step s-1) through a 3-buffer cp.async pipeline into fp16
// m16n8k16 mma (single pass). One grid barrier per interval. Blocks 0..31 run
// the FC head after the final barrier.
__global__ void __launch_bounds__(128, 1) lstm_all(
    const float* __restrict__ input,
    const float* __restrict__ l1_Wx, const float* __restrict__ l1_bx,
    const float* __restrict__ l1_Wh, const float* __restrict__ l1_bh,
    const float* __restrict__ l2_Wx, const float* __restrict__ l2_bx,
    const float* __restrict__ l2_Wh, const float* __restrict__ l2_bh,
    const float* __restrict__ fc1_W, const float* __restrict__ fc1_b,
    const float* __restrict__ fc2_W, const float* __restrict__ fc2_b,
    const float* __restrict__ fc3_W, const float* __restrict__ fc3_b,
    float* __restrict__ out)
{
    extern __shared__ unsigned char dsm[];
    __shared__ float s_bias[2][64];

    const int tid = threadIdx.x;
    const int l = tid & 31;
    const int w = tid >> 5;
    const int mh = blockIdx.x >> 5;       // 0..3
    const int jb = blockIdx.x & 31;       // 0..31
    const uint32_t bufu = smem_u32_(dsm);

    // ================= prep phase (distributed across grid) =================
    {
        const int gi = blockIdx.x * 128 + tid;
        const int gs = NCTA * 128;

        for (int i = gi; i < 4 * H_; i += gs) {
            g_bias1[i] = l1_bx[i] + l1_bh[i];
            g_bias2[i] = l2_bx[i] + l2_bh[i];
        }
        // zero h images slot 0 (initial state)
        {
            const int n16 = (4 * 8 * IMG) / 16;
            uint4 z = make_uint4(0, 0, 0, 0);
            uint4* p1 = (uint4*)&g_h1im[0][0][0][0];
            uint4* p2 = (uint4*)&g_h2im[0][0][0][0];
            for (int i = gi; i < n16; i += gs) { p1[i] = z; p2[i] = z; }
        }
        // layer-1 B images
        for (int e = gi; e < 32 * KT1 * 64 * 8; e += gs) {
            int k8 = e & 7, nrow = (e >> 3) & 63, c = (e >> 9) % KT1, jbx = (e >> 9) / KT1;
            int R = (nrow >> 4) * H_ + jbx * 16 + (nrow & 15);
            float v[8];
            int nv;
            if (c == 0) {
                nv = 0;
                #pragma unroll
                for (int q = 0; q < 8; q++) {
                    int k = k8 * 8 + q;
                    v[q] = (k < IN_) ? l1_Wx[R * IN_ + k] : 0.0f;
                }
                nv = 8;
            } else {
                #pragma unroll
                for (int q = 0; q < 8; q++) v[q] = l1_Wh[R * H_ + (c - 1) * 64 + k8 * 8 + q];
                nv = 8;
            }
            uint32_t u4[4];
            pk8_(v, nv, u4);
            *(uint4*)&g_Bim1[jbx][c][swz_((uint32_t)(nrow * 128 + k8 * 16))] =
                make_uint4(u4[0], u4[1], u4[2], u4[3]);
        }
        // layer-2 B images
        for (int e = gi; e < 32 * KT2 * 64 * 8; e += gs) {
            int k8 = e & 7, nrow = (e >> 3) & 63, c = (e >> 9) & 15, jbx = e >> 13;
            int R = (nrow >> 4) * H_ + jbx * 16 + (nrow & 15);
            float v[8];
            #pragma unroll
            for (int q = 0; q < 8; q++)
                v[q] = (c < 8) ? l2_Wx[R * H_ + c * 64 + k8 * 8 + q]
                               : l2_Wh[R * H_ + (c - 8) * 64 + k8 * 8 + q];
            uint32_t u4[4];
            pk8_(v, 8, u4);
            *(uint4*)&g_Bim2[jbx][c][swz_((uint32_t)(nrow * 128 + k8 * 16))] =
                make_uint4(u4[0], u4[1], u4[2], u4[3]);
        }
        // input A images
        for (int e = gi; e < T_ * 4 * 64 * 8; e += gs) {
            int k8 = e & 7, r = (e >> 3) & 63, mhh = (e >> 9) & 3, t = e >> 11;
            int b = mhh * 64 + r;
            float v[8];
            #pragma unroll
            for (int q = 0; q < 8; q++) {
                int k = k8 * 8 + q;
                v[q] = (k < IN_) ? input[(size_t)b * (T_ * IN_) + t * IN_ + k] : 0.0f;
            }
            uint32_t u4[4];
            pk8_(v, 8, u4);
            *(uint4*)&g_Ain[t][mhh][swz_((uint32_t)(r * 128 + k8 * 16))] =
                make_uint4(u4[0], u4[1], u4[2], u4[3]);
        }
    }
    gbar_();   // prep visible everywhere

    if (tid < 128) {
        int layer = tid >> 6, i = tid & 63;
        const float* bsrc = layer ? g_bias2 : g_bias1;
        s_bias[layer][i] = bsrc[(i >> 4) * H_ + jb * 16 + (i & 15)];
    }
    __syncthreads();

    // ================= persistent recurrence =================
    float c1[8], c2[8];
    #pragma unroll
    for (int i = 0; i < 8; i++) { c1[i] = 0.0f; c2[i] = 0.0f; }

    for (int s = 0; s <= T_; s++) {
        const bool hasL1 = (s < T_), hasL2 = (s >= 1);
        const int n1 = hasL1 ? KT1 : 0;
        const int nch = n1 + (hasL2 ? KT2 : 0);

        {   // prologue: issue chunks 0,1
            const uint4 *ah, *bh;
            chunk_src_(0, n1, s, mh, jb, ah, bh);
            issue_chunk_(bufu, ah, bh, tid);
            chunk_src_(1, n1, s, mh, jb, ah, bh);
            issue_chunk_(bufu + BUFSZ, ah, bh, tid);
        }

        float acc[8][4];
        for (int cc = 0; cc < nch; cc++) {
            if (cc < nch - 1) asm volatile("cp.async.wait_group 1;" ::: "memory");
            else              asm volatile("cp.async.wait_group 0;" ::: "memory");
            __syncthreads();

            if (cc + 2 < nch) {
                const uint4 *ah, *bh;
                chunk_src_(cc + 2, n1, s, mh, jb, ah, bh);
                issue_chunk_(bufu + ((cc + 2) % 3) * BUFSZ, ah, bh, tid);
            }

            if (cc == 0 || cc == n1) {
                #pragma unroll
                for (int nt = 0; nt < 8; nt++)
                    #pragma unroll
                    for (int r = 0; r < 4; r++) acc[nt][r] = 0.0f;
            }

            compute_chunk_(bufu + (cc % 3) * BUFSZ, acc, l, w);

            if (hasL1 && cc == n1 - 1)
                epilogue_(acc, c1, s_bias[0], 0, s, mh, jb, w, l, false);
            if (hasL2 && cc == nch - 1)
                epilogue_(acc, c2, s_bias[1], 1, s - 1, mh, jb, w, l, (s - 1) == T_ - 1);
        }
        gbar_();
    }

    // ================= FC head (blocks 0..31, 8 batches each) ================
    if (blockIdx.x < 32) {
        float* hv = (float*)dsm;             // [8][512]
        float* o1 = hv + 8 * 512;            // [8][256]
        float* o2 = o1 + 8 * 256;            // [8][128]
        const int b0 = blockIdx.x * 8;

        for (int i = tid; i < 8 * 512; i += 128)
            hv[i] = g_h2fin[b0 + (i >> 9)][i & 511];
        __syncthreads();

        for (int o = tid; o < 256; o += 128) {
            float acc[8] = {};
            const float* wp = &fc1_W[o * 512];
            for (int k = 0; k < 512; k++) {
                float wv = wp[k];
                #pragma unroll
                for (int q = 0; q < 8; q++) acc[q] += wv * hv[q * 512 + k];
            }
            float bb = fc1_b[o];
            #pragma unroll
            for (int q = 0; q < 8; q++) o1[q * 256 + o] = fmaxf(acc[q] + bb, 0.0f);
        }
        __syncthreads();

        if (tid < 128) {
            float acc[8] = {};
            const float* wp = &fc2_W[tid * 256];
            for (int k = 0; k < 256; k++) {
                float wv = wp[k];
                #pragma unroll
                for (int q = 0; q < 8; q++) acc[q] += wv * o1[q * 256 + k];
            }
            float bb = fc2_b[tid];
            #pragma unroll
            for (int q = 0; q < 8; q++) o2[q * 128 + tid] = fmaxf(acc[q] + bb, 0.0f);
        }
        __syncthreads();

        if (tid < 8) {
            float sacc = 0.0f;
            for (int k = 0; k < 128; k++) sacc += fc3_W[k] * o2[tid * 128 + k];
            out[b0 + tid] = sacc + fc3_b[0];
        }
    }
}

// ---------------- launch -----------------------------------------------------
extern "C" void kernel_launch(void* const* d_in, const int* in_sizes, int n_in,
                              void* d_out, int out_size)
{
    const float* input  = (const float*)d_in[0];
    const float* l1_Wx  = (const float*)d_in[1];
    const float* l1_bx  = (const float*)d_in[2];
    const float* l1_Wh  = (const float*)d_in[3];
    const float* l1_bh  = (const float*)d_in[4];
    const float* l2_Wx  = (const float*)d_in[5];
    const float* l2_bx  = (const float*)d_in[6];
    const float* l2_Wh  = (const float*)d_in[7];
    const float* l2_bh  = (const float*)d_in[8];
    const float* fc1_W  = (const float*)d_in[9];
    const float* fc1_b  = (const float*)d_in[10];
    const float* fc2_W  = (const float*)d_in[11];
    const float* fc2_b  = (const float*)d_in[12];
    const float* fc3_W  = (const float*)d_in[13];
    const float* fc3_b  = (const float*)d_in[14];

    cudaFuncSetAttribute(lstm_all,
                         cudaFuncAttributeMaxDynamicSharedMemorySize, SMEM_DYN);

    lstm_all<<<NCTA, 128, SMEM_DYN>>>(input,
        l1_Wx, l1_bx, l1_Wh, l1_bh, l2_Wx, l2_bx, l2_Wh, l2_bh,
        fc1_W, fc1_b, fc2_W, fc2_b, fc3_W, fc3_b, (float*)d_out);
}

// round 9
// speedup vs baseline: 6.7264x; 1.0130x over previous
#include <cuda_runtime.h>
#include <cuda_fp16.h>
#include <math.h>
#include <stdint.h>

#define B_   256
#define T_   512
#define IN_  19
#define H_   512
#define KT1  9         // layer-1 chunks: 1 input + 8 hidden
#define KT2  16        // layer-2 chunks: 8 h1 + 8 h2
#define IMG  8192      // 64x64 fp16 swizzled image bytes (64 rows x 128B)
#define NCTA 128
#define BUFSZ 16384    // per-chunk smem: A 8K | B 8K
#define GRPBUF (3 * BUFSZ)          // 48KB per warpgroup
#define PARTIAL_OFF (2 * GRPBUF)    // fp32 partial acc (16KB) at 96KB
#define SMEM_DYN (116 * 1024)       // 96KB buffers + 16KB partial + pad; 1 CTA/SM

// ---------------- static device scratch (no allocs allowed) ----------------
__device__ __align__(16) unsigned char g_Bim1[32][KT1][IMG];   // [jb][chunk]
__device__ __align__(16) unsigned char g_Bim2[32][KT2][IMG];
__device__ __align__(16) unsigned char g_Ain[T_][4][IMG];      // [t][mh]
__device__ __align__(16) unsigned char g_h1im[2][4][8][IMG];   // [slot][mh][jchunk]
__device__ __align__(16) unsigned char g_h2im[2][4][8][IMG];
__device__ float g_bias1[4 * H_], g_bias2[4 * H_];
__device__ float g_h2fin[B_][H_];
__device__ volatile unsigned g_count;
__device__ volatile unsigned g_gen;

// ---------------- helpers ---------------------------------------------------
__device__ __forceinline__ uint32_t swz_(uint32_t o) { return o ^ ((o >> 3) & 0x70); }
__device__ __forceinline__ float tanha_(float x) {
    float y;
    asm("tanh.approx.f32 %0, %1;" : "=f"(y) : "f"(x));
    return y;
}
__device__ __forceinline__ float sigm_(float x) { return 0.5f * tanha_(0.5f * x) + 0.5f; }

__device__ __forceinline__ uint32_t smem_u32_(const void* p) {
    uint32_t a;
    asm("{ .reg .u64 t; cvta.to.shared.u64 t, %1; cvt.u32.u64 %0, t; }" : "=r"(a) : "l"(p));
    return a;
}
__device__ __forceinline__ void ldsm4_(uint32_t* r, uint32_t a) {
    asm volatile("ldmatrix.sync.aligned.m8n8.x4.shared.b16 {%0,%1,%2,%3}, [%4];"
        : "=r"(r[0]), "=r"(r[1]), "=r"(r[2]), "=r"(r[3]) : "r"(a));
}
__device__ __forceinline__ void mma_(float* d, const uint32_t* a, const uint32_t* b) {
    asm volatile("mma.sync.aligned.m16n8k16.row.col.f32.f16.f16.f32 "
        "{%0,%1,%2,%3}, {%4,%5,%6,%7}, {%8,%9}, {%0,%1,%2,%3};"
        : "+f"(d[0]), "+f"(d[1]), "+f"(d[2]), "+f"(d[3])
        : "r"(a[0]), "r"(a[1]), "r"(a[2]), "r"(a[3]), "r"(b[0]), "r"(b[1]));
}
__device__ __forceinline__ void cpa_(uint32_t sa, const void* ga) {
    asm volatile("cp.async.cg.shared.global [%0], [%1], 16;" :: "r"(sa), "l"(ga));
}
__device__ __forceinline__ void pk8_(const float* v, uint32_t* out4) {
    #pragma unroll
    for (int q = 0; q < 4; q++) {
        unsigned short h0 = __half_as_ushort(__float2half_rn(v[2 * q]));
        unsigned short h1 = __half_as_ushort(__float2half_rn(v[2 * q + 1]));
        out4[q] = (uint32_t)h0 | ((uint32_t)h1 << 16);
    }
}

// ---------------- grid barrier (self-resetting, replay-safe) -----------------
__device__ __forceinline__ void gbar_() {
    __syncthreads();
    if (threadIdx.x == 0) {
        __threadfence();
        unsigned gen = g_gen;
        if (atomicAdd((unsigned*)&g_count, 1u) == NCTA - 1u) {
            g_count = 0;
            __threadfence();
            g_gen = gen + 1u;
        } else {
            while (g_gen == gen) { }
        }
        __threadfence();
    }
    __syncthreads();
}

// ---------------- chunk source (per warpgroup) -------------------------------
// group 0: [0..nL1) = L1 chunks, [nL1..nL1+3) = L2 chunks 0..2
// group 1: i -> L2 chunk 3+i  (3..15)
__device__ __forceinline__ void chunk_src_g_(int g, int i, int nL1, int s, int mh, int jb,
    const uint4*& ah, const uint4*& bh)
{
    if (g == 0) {
        if (i < nL1) {
            if (i == 0) ah = (const uint4*)g_Ain[s][mh];
            else        ah = (const uint4*)g_h1im[s & 1][mh][i - 1];
            bh = (const uint4*)g_Bim1[jb][i];
        } else {
            int c = i - nL1;                       // 0..2 -> h1 sources
            ah = (const uint4*)g_h1im[s & 1][mh][c];
            bh = (const uint4*)g_Bim2[jb][c];
        }
    } else {
        int c = 3 + i;                             // 3..15
        if (c < 8) ah = (const uint4*)g_h1im[s & 1][mh][c];
        else       ah = (const uint4*)g_h2im[(s - 1) & 1][mh][c - 8];
        bh = (const uint4*)g_Bim2[jb][c];
    }
}

__device__ __forceinline__ void issue_chunk_(uint32_t sbuf, const uint4* ah, const uint4* bh, int gt)
{
    #pragma unroll
    for (int i = 0; i < 4; i++) {
        int e = gt + i * 128;
        cpa_(sbuf + e * 16,        ah + e);
        cpa_(sbuf + 8192 + e * 16, bh + e);
    }
    asm volatile("cp.async.commit_group;" ::: "memory");
}

// ---------------- one chunk of MMA: single-pass fp16 -------------------------
__device__ __forceinline__ void compute_chunk_(uint32_t sbuf, float acc[8][4], int l, int w)
{
    const uint32_t arow  = (uint32_t)(w * 16 + (l & 15));
    const uint32_t abyte = (uint32_t)(((l >> 4) & 1) * 16);
    const uint32_t brow0 = (uint32_t)(((l >> 4) & 1) * 8 + (l & 7));
    const uint32_t bbyte = (uint32_t)(((l >> 3) & 1) * 16);

    #pragma unroll
    for (int ks = 0; ks < 4; ks++) {
        uint32_t a4[4];
        ldsm4_(a4, sbuf + swz_(arow * 128 + (uint32_t)ks * 32 + abyte));
        #pragma unroll
        for (int tp = 0; tp < 4; tp++) {
            uint32_t b4[4];
            ldsm4_(b4, sbuf + 8192 + swz_(((uint32_t)tp * 16 + brow0) * 128 + (uint32_t)ks * 32 + bbyte));
            mma_(acc[2 * tp],     a4, b4);
            mma_(acc[2 * tp + 1], a4, b4 + 2);
        }
    }
}

// ---------------- fused LSTM cell epilogue -----------------------------------
__device__ __forceinline__ void epilogue_(float acc[8][4], float* cst, const float* sb,
    int layer, int t, int mh, int jb, int w, int l, bool lastw)
{
    unsigned char* hb0 = (layer ? g_h2im : g_h1im)[(t + 1) & 1][mh][jb >> 2];

    #pragma unroll
    for (int a = 0; a < 2; a++) {
        #pragma unroll
        for (int rh = 0; rh < 2; rh++) {
            int row = 16 * w + (l >> 2) + rh * 8;
            unsigned short hf[2];
            #pragma unroll
            for (int b = 0; b < 2; b++) {
                int jj = 8 * a + 2 * (l & 3) + b;
                float pi = acc[a][rh * 2 + b]     + sb[jj];
                float pf = acc[a + 2][rh * 2 + b] + sb[16 + jj];
                float pg = acc[a + 4][rh * 2 + b] + sb[32 + jj];
                float po = acc[a + 6][rh * 2 + b] + sb[48 + jj];
                int ci = a * 4 + rh * 2 + b;
                float cc = sigm_(pf) * cst[ci] + sigm_(pi) * tanha_(pg);
                cst[ci] = cc;
                float h = sigm_(po) * tanha_(cc);
                hf[b] = __half_as_ushort(__float2half_rn(h));
                if (lastw) g_h2fin[mh * 64 + row][jb * 16 + jj] = h;
            }
            uint32_t off = swz_((uint32_t)(row * 128 + ((jb & 3) * 16 + 8 * a + 2 * (l & 3)) * 2));
            *(uint32_t*)(hb0 + off) = (uint32_t)hf[0] | ((uint32_t)hf[1] << 16);
        }
    }
}

// ---------------- THE kernel: prep + dual-warpgroup persistent LSTM + head ---
// 128 CTAs x 256 threads, 1/SM. CTA owns a 64-row x 16-j tile of BOTH layers.
// Warpgroup 0 (warps 0-3): 9 L1 chunks -> L1 epilogue -> 3 L2 chunks -> fp32
// partial to smem. Warpgroup 1 (warps 4-7): 13 L2 chunks -> bar.sync 3 ->
// merge partial -> L2 epilogue. Serial chain per interval: 13 chunks (was 25).
__global__ void __launch_bounds__(256, 1) lstm_all(
    const float* __restrict__ input,
    const float* __restrict__ l1_Wx, const float* __restrict__ l1_bx,
    const float* __restrict__ l1_Wh, const float* __restrict__ l1_bh,
    const float* __restrict__ l2_Wx, const float* __restrict__ l2_bx,
    const float* __restrict__ l2_Wh, const float* __restrict__ l2_bh,
    const float* __restrict__ fc1_W, const float* __restrict__ fc1_b,
    const float* __restrict__ fc2_W, const float* __restrict__ fc2_b,
    const float* __restrict__ fc3_W, const float* __restrict__ fc3_b,
    float* __restrict__ out)
{
    extern __shared__ unsigned char dsm[];
    __shared__ float s_bias[2][64];

    const int tid = threadIdx.x;
    const int g  = tid >> 7;          // warpgroup 0/1
    const int gt = tid & 127;
    const int l  = gt & 31;
    const int w  = gt >> 5;
    const int mh = blockIdx.x >> 5;   // 0..3
    const int jb = blockIdx.x & 31;   // 0..31
    const uint32_t bufu = smem_u32_(dsm);
    const uint32_t gbuf = bufu + (uint32_t)g * GRPBUF;
    float* pp = (float*)(dsm + PARTIAL_OFF);

    // ================= prep phase (distributed across grid) =================
    {
        const int gi = blockIdx.x * 256 + tid;
        const int gs = NCTA * 256;

        for (int i = gi; i < 4 * H_; i += gs) {
            g_bias1[i] = l1_bx[i] + l1_bh[i];
            g_bias2[i] = l2_bx[i] + l2_bh[i];
        }
        {
            const int n16 = (4 * 8 * IMG) / 16;
            uint4 z = make_uint4(0, 0, 0, 0);
            uint4* p1 = (uint4*)&g_h1im[0][0][0][0];
            uint4* p2 = (uint4*)&g_h2im[0][0][0][0];
            for (int i = gi; i < n16; i += gs) { p1[i] = z; p2[i] = z; }
        }
        for (int e = gi; e < 32 * KT1 * 64 * 8; e += gs) {
            int k8 = e & 7, nrow = (e >> 3) & 63, c = (e >> 9) % KT1, jbx = (e >> 9) / KT1;
            int R = (nrow >> 4) * H_ + jbx * 16 + (nrow & 15);
            float v[8];
            #pragma unroll
            for (int q = 0; q < 8; q++) {
                int k = k8 * 8 + q;
                v[q] = (c == 0) ? ((k < IN_) ? l1_Wx[R * IN_ + k] : 0.0f)
                                : l1_Wh[R * H_ + (c - 1) * 64 + k];
            }
            uint32_t u4[4];
            pk8_(v, u4);
            *(uint4*)&g_Bim1[jbx][c][swz_((uint32_t)(nrow * 128 + k8 * 16))] =
                make_uint4(u4[0], u4[1], u4[2], u4[3]);
        }
        for (int e = gi; e < 32 * KT2 * 64 * 8; e += gs) {
            int k8 = e & 7, nrow = (e >> 3) & 63, c = (e >> 9) & 15, jbx = e >> 13;
            int R = (nrow >> 4) * H_ + jbx * 16 + (nrow & 15);
            float v[8];
            #pragma unroll
            for (int q = 0; q < 8; q++)
                v[q] = (c < 8) ? l2_Wx[R * H_ + c * 64 + k8 * 8 + q]
                               : l2_Wh[R * H_ + (c - 8) * 64 + k8 * 8 + q];
            uint32_t u4[4];
            pk8_(v, u4);
            *(uint4*)&g_Bim2[jbx][c][swz_((uint32_t)(nrow * 128 + k8 * 16))] =
                make_uint4(u4[0], u4[1], u4[2], u4[3]);
        }
        for (int e = gi; e < T_ * 4 * 64 * 8; e += gs) {
            int k8 = e & 7, r = (e >> 3) & 63, mhh = (e >> 9) & 3, t = e >> 11;
            int b = mhh * 64 + r;
            float v[8];
            #pragma unroll
            for (int q = 0; q < 8; q++) {
                int k = k8 * 8 + q;
                v[q] = (k < IN_) ? input[(size_t)b * (T_ * IN_) + t * IN_ + k] : 0.0f;
            }
            uint32_t u4[4];
            pk8_(v, u4);
            *(uint4*)&g_Ain[t][mhh][swz_((uint32_t)(r * 128 + k8 * 16))] =
                make_uint4(u4[0], u4[1], u4[2], u4[3]);
        }
    }
    gbar_();   // prep visible everywhere

    if (tid < 128) {
        int layer = tid >> 6, i = tid & 63;
        const float* bsrc = layer ? g_bias2 : g_bias1;
        s_bias[layer][i] = bsrc[(i >> 4) * H_ + jb * 16 + (i & 15)];
    }
    __syncthreads();

    // ================= persistent recurrence =================
    float cst[8];
    #pragma unroll
    for (int i = 0; i < 8; i++) cst[i] = 0.0f;   // g0: c1, g1: c2

    for (int s = 0; s <= T_; s++) {
        const bool hasL1 = (s < T_), hasL2 = (s >= 1);
        const int nL1 = hasL1 ? KT1 : 0;
        const int ntot = (g == 0) ? nL1 + (hasL2 ? 3 : 0)
                                  : (hasL2 ? 13 : 0);

        float acc[8][4];
        if (ntot > 0) {
            {   // prologue: issue chunks 0,1
                const uint4 *ah, *bh;
                chunk_src_g_(g, 0, nL1, s, mh, jb, ah, bh);
                issue_chunk_(gbuf, ah, bh, gt);
                if (ntot > 1) {
                    chunk_src_g_(g, 1, nL1, s, mh, jb, ah, bh);
                    issue_chunk_(gbuf + BUFSZ, ah, bh, gt);
                }
            }
            for (int i = 0; i < ntot; i++) {
                if (i < ntot - 1) asm volatile("cp.async.wait_group 1;" ::: "memory");
                else              asm volatile("cp.async.wait_group 0;" ::: "memory");
                asm volatile("bar.sync %0, 128;" :: "r"(1 + g) : "memory");

                if (i + 2 < ntot) {
                    const uint4 *ah, *bh;
                    chunk_src_g_(g, i + 2, nL1, s, mh, jb, ah, bh);
                    issue_chunk_(gbuf + ((i + 2) % 3) * BUFSZ, ah, bh, gt);
                }

                if (i == 0 || (g == 0 && i == nL1)) {
                    #pragma unroll
                    for (int nt = 0; nt < 8; nt++)
                        #pragma unroll
                        for (int r = 0; r < 4; r++) acc[nt][r] = 0.0f;
                }

                compute_chunk_(gbuf + (i % 3) * BUFSZ, acc, l, w);

                if (g == 0 && hasL1 && i == nL1 - 1)
                    epilogue_(acc, cst, s_bias[0], 0, s, mh, jb, w, l, false);
            }
        }

        if (hasL2) {
            if (g == 0) {   // publish 3-chunk L2 partial
                float* pd = pp + gt * 32;
                #pragma unroll
                for (int nt = 0; nt < 8; nt++)
                    #pragma unroll
                    for (int r = 0; r < 4; r++) pd[nt * 4 + r] = acc[nt][r];
            }
            asm volatile("bar.sync 3, 256;" ::: "memory");
            if (g == 1) {   // merge + epilogue
                const float* ps = pp + gt * 32;
                #pragma unroll
                for (int nt = 0; nt < 8; nt++)
                    #pragma unroll
                    for (int r = 0; r < 4; r++) acc[nt][r] += ps[nt * 4 + r];
                epilogue_(acc, cst, s_bias[1], 1, s - 1, mh, jb, w, l, (s - 1) == T_ - 1);
            }
        }
        gbar_();
    }

    // ================= FC head (blocks 0..31, 8 batches each) ================
    if (blockIdx.x < 32) {
        float* hv = (float*)dsm;             // [8][512]
        float* o1 = hv + 8 * 512;            // [8][256]
        float* o2 = o1 + 8 * 256;            // [8][128]
        const int b0 = blockIdx.x * 8;

        for (int i = tid; i < 8 * 512; i += 256)
            hv[i] = g_h2fin[b0 + (i >> 9)][i & 511];
        __syncthreads();

        {
            float acc[8] = {};
            const float* wp = &fc1_W[tid * 512];
            for (int k = 0; k < 512; k++) {
                float wv = wp[k];
                #pragma unroll
                for (int q = 0; q < 8; q++) acc[q] += wv * hv[q * 512 + k];
            }
            float bb = fc1_b[tid];
            #pragma unroll
            for (int q = 0; q < 8; q++) o1[q * 256 + tid] = fmaxf(acc[q] + bb, 0.0f);
        }
        __syncthreads();

        if (tid < 128) {
            float acc[8] = {};
            const float* wp = &fc2_W[tid * 256];
            for (int k = 0; k < 256; k++) {
                float wv = wp[k];
                #pragma unroll
                for (int q = 0; q < 8; q++) acc[q] += wv * o1[q * 256 + k];
            }
            float bb = fc2_b[tid];
            #pragma unroll
            for (int q = 0; q < 8; q++) o2[q * 128 + tid] = fmaxf(acc[q] + bb, 0.0f);
        }
        __syncthreads();

        if (tid < 8) {
            float sacc = 0.0f;
            for (int k = 0; k < 128; k++) sacc += fc3_W[k] * o2[tid * 128 + k];
            out[b0 + tid] = sacc + fc3_b[0];
        }
    }
}

// ---------------- launch -----------------------------------------------------
extern "C" void kernel_launch(void* const* d_in, const int* in_sizes, int n_in,
                              void* d_out, int out_size)
{
    const float* input  = (const float*)d_in[0];
    const float* l1_Wx  = (const float*)d_in[1];
    const float* l1_bx  = (const float*)d_in[2];
    const float* l1_Wh  = (const float*)d_in[3];
    const float* l1_bh  = (const float*)d_in[4];
    const float* l2_Wx  = (const float*)d_in[5];
    const float* l2_bx  = (const float*)d_in[6];
    const float* l2_Wh  = (const float*)d_in[7];
    const float* l2_bh  = (const float*)d_in[8];
    const float* fc1_W  = (const float*)d_in[9];
    const float* fc1_b  = (const float*)d_in[10];
    const float* fc2_W  = (const float*)d_in[11];
    const float* fc2_b  = (const float*)d_in[12];
    const float* fc3_W  = (const float*)d_in[13];
    const float* fc3_b  = (const float*)d_in[14];

    cudaFuncSetAttribute(lstm_all,
                         cudaFuncAttributeMaxDynamicSharedMemorySize, SMEM_DYN);

    lstm_all<<<NCTA, 256, SMEM_DYN>>>(input,
        l1_Wx, l1_bx, l1_Wh, l1_bh, l2_Wx, l2_bx, l2_Wh, l2_bh,
        fc1_W, fc1_b, fc2_W, fc2_b, fc3_W, fc3_b, (float*)d_out);
}

// round 10
// speedup vs baseline: 6.7458x; 1.0029x over previous
#include <cuda_runtime.h>
#include <cuda_fp16.h>
#include <math.h>
#include <stdint.h>

#define B_   256
#define T_   512
#define IN_  19
#define H_   512
#define KT1  9         // layer-1 chunks: 1 input + 8 hidden
#define KT2  16        // layer-2 chunks: 8 h1 + 8 h2
#define IMG  8192      // 64x64 fp16 swizzled image bytes (64 rows x 128B)
#define NCTA 128
#define BUFSZ 16384    // per-chunk smem: A 8K | B 8K
#define GRPBUF (3 * BUFSZ)          // 48KB per warpgroup
#define PARTIAL_OFF (2 * GRPBUF)    // fp32 partial acc (16KB) at 96KB
#define SMEM_DYN (116 * 1024)       // 96KB buffers + 16KB partial + pad; 1 CTA/SM

// ---------------- static device scratch (no allocs allowed) ----------------
__device__ __align__(16) unsigned char g_Bim1[32][KT1][IMG];   // [jb][chunk]
__device__ __align__(16) unsigned char g_Bim2[32][KT2][IMG];
__device__ __align__(16) unsigned char g_Ain[T_][4][IMG];      // [t][mh]
__device__ __align__(16) unsigned char g_h1im[2][4][8][IMG];   // [slot][mh][jchunk]
__device__ __align__(16) unsigned char g_h2im[2][4][8][IMG];
__device__ float g_bias1[4 * H_], g_bias2[4 * H_];
__device__ float g_h2fin[B_][H_];
__device__ volatile unsigned g_count;
__device__ volatile unsigned g_gen;

// ---------------- helpers ---------------------------------------------------
__device__ __forceinline__ uint32_t swz_(uint32_t o) { return o ^ ((o >> 3) & 0x70); }

// packed f16x2 activations: MUFU cost halved vs f32 (2 cells per op)
__device__ __forceinline__ __half2 tanh2_(__half2 x) {
    __half2 y;
    asm("tanh.approx.f16x2 %0, %1;" : "=r"(*(uint32_t*)&y) : "r"(*(const uint32_t*)&x));
    return y;
}
__device__ __forceinline__ __half2 sigm2_(__half2 x) {
    const __half2 hhalf = __float2half2_rn(0.5f);
    return __hfma2(tanh2_(__hmul2(x, hhalf)), hhalf, hhalf);
}

__device__ __forceinline__ uint32_t smem_u32_(const void* p) {
    uint32_t a;
    asm("{ .reg .u64 t; cvta.to.shared.u64 t, %1; cvt.u32.u64 %0, t; }" : "=r"(a) : "l"(p));
    return a;
}
__device__ __forceinline__ void ldsm4_(uint32_t* r, uint32_t a) {
    asm volatile("ldmatrix.sync.aligned.m8n8.x4.shared.b16 {%0,%1,%2,%3}, [%4];"
        : "=r"(r[0]), "=r"(r[1]), "=r"(r[2]), "=r"(r[3]) : "r"(a));
}
__device__ __forceinline__ void mma_(float* d, const uint32_t* a, const uint32_t* b) {
    asm volatile("mma.sync.aligned.m16n8k16.row.col.f32.f16.f16.f32 "
        "{%0,%1,%2,%3}, {%4,%5,%6,%7}, {%8,%9}, {%0,%1,%2,%3};"
        : "+f"(d[0]), "+f"(d[1]), "+f"(d[2]), "+f"(d[3])
        : "r"(a[0]), "r"(a[1]), "r"(a[2]), "r"(a[3]), "r"(b[0]), "r"(b[1]));
}
__device__ __forceinline__ void cpa_(uint32_t sa, const void* ga) {
    asm volatile("cp.async.cg.shared.global [%0], [%1], 16;" :: "r"(sa), "l"(ga));
}
__device__ __forceinline__ void pk8_(const float* v, uint32_t* out4) {
    #pragma unroll
    for (int q = 0; q < 4; q++) {
        unsigned short h0 = __half_as_ushort(__float2half_rn(v[2 * q]));
        unsigned short h1 = __half_as_ushort(__float2half_rn(v[2 * q + 1]));
        out4[q] = (uint32_t)h0 | ((uint32_t)h1 << 16);
    }
}

// ---------------- grid barrier (self-resetting, replay-safe) -----------------
__device__ __forceinline__ void gbar_() {
    __syncthreads();
    if (threadIdx.x == 0) {
        __threadfence();
        unsigned gen = g_gen;
        if (atomicAdd((unsigned*)&g_count, 1u) == NCTA - 1u) {
            g_count = 0;
            __threadfence();
            g_gen = gen + 1u;
        } else {
            while (g_gen == gen) { }
        }
        __threadfence();
    }
    __syncthreads();
}

// ---------------- chunk source (per warpgroup) -------------------------------
// group 0: [0..nL1) = L1 chunks, [nL1..nL1+3) = L2 chunks 0..2
// group 1: i -> L2 chunk 3+i  (3..15)
__device__ __forceinline__ void chunk_src_g_(int g, int i, int nL1, int s, int mh, int jb,
    const uint4*& ah, const uint4*& bh)
{
    if (g == 0) {
        if (i < nL1) {
            if (i == 0) ah = (const uint4*)g_Ain[s][mh];
            else        ah = (const uint4*)g_h1im[s & 1][mh][i - 1];
            bh = (const uint4*)g_Bim1[jb][i];
        } else {
            int c = i - nL1;                       // 0..2 -> h1 sources
            ah = (const uint4*)g_h1im[s & 1][mh][c];
            bh = (const uint4*)g_Bim2[jb][c];
        }
    } else {
        int c = 3 + i;                             // 3..15
        if (c < 8) ah = (const uint4*)g_h1im[s & 1][mh][c];
        else       ah = (const uint4*)g_h2im[(s - 1) & 1][mh][c - 8];
        bh = (const uint4*)g_Bim2[jb][c];
    }
}

__device__ __forceinline__ void issue_chunk_(uint32_t sbuf, const uint4* ah, const uint4* bh, int gt)
{
    #pragma unroll
    for (int i = 0; i < 4; i++) {
        int e = gt + i * 128;
        cpa_(sbuf + e * 16,        ah + e);
        cpa_(sbuf + 8192 + e * 16, bh + e);
    }
    asm volatile("cp.async.commit_group;" ::: "memory");
}

// ---------------- one chunk of MMA: single-pass fp16 -------------------------
__device__ __forceinline__ void compute_chunk_(uint32_t sbuf, float acc[8][4], int l, int w)
{
    const uint32_t arow  = (uint32_t)(w * 16 + (l & 15));
    const uint32_t abyte = (uint32_t)(((l >> 4) & 1) * 16);
    const uint32_t brow0 = (uint32_t)(((l >> 4) & 1) * 8 + (l & 7));
    const uint32_t bbyte = (uint32_t)(((l >> 3) & 1) * 16);

    #pragma unroll
    for (int ks = 0; ks < 4; ks++) {
        uint32_t a4[4];
        ldsm4_(a4, sbuf + swz_(arow * 128 + (uint32_t)ks * 32 + abyte));
        #pragma unroll
        for (int tp = 0; tp < 4; tp++) {
            uint32_t b4[4];
            ldsm4_(b4, sbuf + 8192 + swz_(((uint32_t)tp * 16 + brow0) * 128 + (uint32_t)ks * 32 + bbyte));
            mma_(acc[2 * tp],     a4, b4);
            mma_(acc[2 * tp + 1], a4, b4 + 2);
        }
    }
}

// ---------------- fused LSTM cell epilogue (f16x2 MUFU path) -----------------
__device__ __forceinline__ void epilogue_(float acc[8][4], float* cst, const float* sb,
    int layer, int t, int mh, int jb, int w, int l, bool lastw)
{
    unsigned char* hb0 = (layer ? g_h2im : g_h1im)[(t + 1) & 1][mh][jb >> 2];

    #pragma unroll
    for (int a = 0; a < 2; a++) {
        #pragma unroll
        for (int rh = 0; rh < 2; rh++) {
            int row = 16 * w + (l >> 2) + rh * 8;
            int jj0 = 8 * a + 2 * (l & 3);
            // pre-activations for the two adjacent cells (b=0,1)
            float pi0 = acc[a][rh * 2 + 0]     + sb[jj0];
            float pi1 = acc[a][rh * 2 + 1]     + sb[jj0 + 1];
            float pf0 = acc[a + 2][rh * 2 + 0] + sb[16 + jj0];
            float pf1 = acc[a + 2][rh * 2 + 1] + sb[16 + jj0 + 1];
            float pg0 = acc[a + 4][rh * 2 + 0] + sb[32 + jj0];
            float pg1 = acc[a + 4][rh * 2 + 1] + sb[32 + jj0 + 1];
            float po0 = acc[a + 6][rh * 2 + 0] + sb[48 + jj0];
            float po1 = acc[a + 6][rh * 2 + 1] + sb[48 + jj0 + 1];

            __half2 si2 = sigm2_(__floats2half2_rn(pi0, pi1));
            __half2 sf2 = sigm2_(__floats2half2_rn(pf0, pf1));
            __half2 tg2 = tanh2_(__floats2half2_rn(pg0, pg1));
            __half2 so2 = sigm2_(__floats2half2_rn(po0, po1));

            float2 si = __half22float2(si2);
            float2 sf = __half22float2(sf2);
            float2 tg = __half22float2(tg2);

            int ci = a * 4 + rh * 2;
            float c0 = sf.x * cst[ci]     + si.x * tg.x;
            float c1 = sf.y * cst[ci + 1] + si.y * tg.y;
            cst[ci] = c0;
            cst[ci + 1] = c1;

            __half2 tc2 = tanh2_(__floats2half2_rn(c0, c1));
            __half2 h2v = __hmul2(so2, tc2);

            uint32_t off = swz_((uint32_t)(row * 128 + ((jb & 3) * 16 + jj0) * 2));
            *(uint32_t*)(hb0 + off) = *(const uint32_t*)&h2v;
            if (lastw) {
                float2 hf = __half22float2(h2v);
                g_h2fin[mh * 64 + row][jb * 16 + jj0]     = hf.x;
                g_h2fin[mh * 64 + row][jb * 16 + jj0 + 1] = hf.y;
            }
        }
    }
}

// ---------------- THE kernel: prep + dual-warpgroup persistent LSTM + head ---
// 128 CTAs x 256 threads, 1/SM. CTA owns a 64-row x 16-j tile of BOTH layers.
// Warpgroup 0 (warps 0-3): 9 L1 chunks -> L1 epilogue -> 3 L2 chunks -> fp32
// partial to smem. Warpgroup 1 (warps 4-7): 13 L2 chunks -> bar.sync 3 ->
// merge partial -> L2 epilogue. Activations run on the f16x2 MUFU path.
__global__ void __launch_bounds__(256, 1) lstm_all(
    const float* __restrict__ input,
    const float* __restrict__ l1_Wx, const float* __restrict__ l1_bx,
    const float* __restrict__ l1_Wh, const float* __restrict__ l1_bh,
    const float* __restrict__ l2_Wx, const float* __restrict__ l2_bx,
    const float* __restrict__ l2_Wh, const float* __restrict__ l2_bh,
    const float* __restrict__ fc1_W, const float* __restrict__ fc1_b,
    const float* __restrict__ fc2_W, const float* __restrict__ fc2_b,
    const float* __restrict__ fc3_W, const float* __restrict__ fc3_b,
    float* __restrict__ out)
{
    extern __shared__ unsigned char dsm[];
    __shared__ float s_bias[2][64];

    const int tid = threadIdx.x;
    const int g  = tid >> 7;          // warpgroup 0/1
    const int gt = tid & 127;
    const int l  = gt & 31;
    const int w  = gt >> 5;
    const int mh = blockIdx.x >> 5;   // 0..3
    const int jb = blockIdx.x & 31;   // 0..31
    const uint32_t bufu = smem_u32_(dsm);
    const uint32_t gbuf = bufu + (uint32_t)g * GRPBUF;
    float* pp = (float*)(dsm + PARTIAL_OFF);

    // ================= prep phase (distributed across grid) =================
    {
        const int gi = blockIdx.x * 256 + tid;
        const int gs = NCTA * 256;

        for (int i = gi; i < 4 * H_; i += gs) {
            g_bias1[i] = l1_bx[i] + l1_bh[i];
            g_bias2[i] = l2_bx[i] + l2_bh[i];
        }
        {
            const int n16 = (4 * 8 * IMG) / 16;
            uint4 z = make_uint4(0, 0, 0, 0);
            uint4* p1 = (uint4*)&g_h1im[0][0][0][0];
            uint4* p2 = (uint4*)&g_h2im[0][0][0][0];
            for (int i = gi; i < n16; i += gs) { p1[i] = z; p2[i] = z; }
        }
        for (int e = gi; e < 32 * KT1 * 64 * 8; e += gs) {
            int k8 = e & 7, nrow = (e >> 3) & 63, c = (e >> 9) % KT1, jbx = (e >> 9) / KT1;
            int R = (nrow >> 4) * H_ + jbx * 16 + (nrow & 15);
            float v[8];
            #pragma unroll
            for (int q = 0; q < 8; q++) {
                int k = k8 * 8 + q;
                v[q] = (c == 0) ? ((k < IN_) ? l1_Wx[R * IN_ + k] : 0.0f)
                                : l1_Wh[R * H_ + (c - 1) * 64 + k];
            }
            uint32_t u4[4];
            pk8_(v, u4);
            *(uint4*)&g_Bim1[jbx][c][swz_((uint32_t)(nrow * 128 + k8 * 16))] =
                make_uint4(u4[0], u4[1], u4[2], u4[3]);
        }
        for (int e = gi; e < 32 * KT2 * 64 * 8; e += gs) {
            int k8 = e & 7, nrow = (e >> 3) & 63, c = (e >> 9) & 15, jbx = e >> 13;
            int R = (nrow >> 4) * H_ + jbx * 16 + (nrow & 15);
            float v[8];
            #pragma unroll
            for (int q = 0; q < 8; q++)
                v[q] = (c < 8) ? l2_Wx[R * H_ + c * 64 + k8 * 8 + q]
                               : l2_Wh[R * H_ + (c - 8) * 64 + k8 * 8 + q];
            uint32_t u4[4];
            pk8_(v, u4);
            *(uint4*)&g_Bim2[jbx][c][swz_((uint32_t)(nrow * 128 + k8 * 16))] =
                make_uint4(u4[0], u4[1], u4[2], u4[3]);
        }
        for (int e = gi; e < T_ * 4 * 64 * 8; e += gs) {
            int k8 = e & 7, r = (e >> 3) & 63, mhh = (e >> 9) & 3, t = e >> 11;
            int b = mhh * 64 + r;
            float v[8];
            #pragma unroll
            for (int q = 0; q < 8; q++) {
                int k = k8 * 8 + q;
                v[q] = (k < IN_) ? input[(size_t)b * (T_ * IN_) + t * IN_ + k] : 0.0f;
            }
            uint32_t u4[4];
            pk8_(v, u4);
            *(uint4*)&g_Ain[t][mhh][swz_((uint32_t)(r * 128 + k8 * 16))] =
                make_uint4(u4[0], u4[1], u4[2], u4[3]);
        }
    }
    gbar_();   // prep visible everywhere

    if (tid < 128) {
        int layer = tid >> 6, i = tid & 63;
        const float* bsrc = layer ? g_bias2 : g_bias1;
        s_bias[layer][i] = bsrc[(i >> 4) * H_ + jb * 16 + (i & 15)];
    }
    __syncthreads();

    // ================= persistent recurrence =================
    float cst[8];
    #pragma unroll
    for (int i = 0; i < 8; i++) cst[i] = 0.0f;   // g0: c1, g1: c2

    for (int s = 0; s <= T_; s++) {
        const bool hasL1 = (s < T_), hasL2 = (s >= 1);
        const int nL1 = hasL1 ? KT1 : 0;
        const int ntot = (g == 0) ? nL1 + (hasL2 ? 3 : 0)
                                  : (hasL2 ? 13 : 0);

        float acc[8][4];
        if (ntot > 0) {
            {   // prologue: issue chunks 0,1
                const uint4 *ah, *bh;
                chunk_src_g_(g, 0, nL1, s, mh, jb, ah, bh);
                issue_chunk_(gbuf, ah, bh, gt);
                if (ntot > 1) {
                    chunk_src_g_(g, 1, nL1, s, mh, jb, ah, bh);
                    issue_chunk_(gbuf + BUFSZ, ah, bh, gt);
                }
            }
            for (int i = 0; i < ntot; i++) {
                if (i < ntot - 1) asm volatile("cp.async.wait_group 1;" ::: "memory");
                else              asm volatile("cp.async.wait_group 0;" ::: "memory");
                asm volatile("bar.sync %0, 128;" :: "r"(1 + g) : "memory");

                if (i + 2 < ntot) {
                    const uint4 *ah, *bh;
                    chunk_src_g_(g, i + 2, nL1, s, mh, jb, ah, bh);
                    issue_chunk_(gbuf + ((i + 2) % 3) * BUFSZ, ah, bh, gt);
                }

                if (i == 0 || (g == 0 && i == nL1)) {
                    #pragma unroll
                    for (int nt = 0; nt < 8; nt++)
                        #pragma unroll
                        for (int r = 0; r < 4; r++) acc[nt][r] = 0.0f;
                }

                compute_chunk_(gbuf + (i % 3) * BUFSZ, acc, l, w);

                if (g == 0 && hasL1 && i == nL1 - 1)
                    epilogue_(acc, cst, s_bias[0], 0, s, mh, jb, w, l, false);
            }
        }

        if (hasL2) {
            if (g == 0) {   // publish 3-chunk L2 partial
                float* pd = pp + gt * 32;
                #pragma unroll
                for (int nt = 0; nt < 8; nt++)
                    #pragma unroll
                    for (int r = 0; r < 4; r++) pd[nt * 4 + r] = acc[nt][r];
            }
            asm volatile("bar.sync 3, 256;" ::: "memory");
            if (g == 1) {   // merge + epilogue
                const float* ps = pp + gt * 32;
                #pragma unroll
                for (int nt = 0; nt < 8; nt++)
                    #pragma unroll
                    for (int r = 0; r < 4; r++) acc[nt][r] += ps[nt * 4 + r];
                epilogue_(acc, cst, s_bias[1], 1, s - 1, mh, jb, w, l, (s - 1) == T_ - 1);
            }
        }
        gbar_();
    }

    // ================= FC head (blocks 0..31, 8 batches each) ================
    if (blockIdx.x < 32) {
        float* hv = (float*)dsm;             // [8][512]
        float* o1 = hv + 8 * 512;            // [8][256]
        float* o2 = o1 + 8 * 256;            // [8][128]
        const int b0 = blockIdx.x * 8;

        for (int i = tid; i < 8 * 512; i += 256)
            hv[i] = g_h2fin[b0 + (i >> 9)][i & 511];
        __syncthreads();

        {
            float acc[8] = {};
            const float* wp = &fc1_W[tid * 512];
            for (int k = 0; k < 512; k++) {
                float wv = wp[k];
                #pragma unroll
                for (int q = 0; q < 8; q++) acc[q] += wv * hv[q * 512 + k];
            }
            float bb = fc1_b[tid];
            #pragma unroll
            for (int q = 0; q < 8; q++) o1[q * 256 + tid] = fmaxf(acc[q] + bb, 0.0f);
        }
        __syncthreads();

        if (tid < 128) {
            float acc[8] = {};
            const float* wp = &fc2_W[tid * 256];
            for (int k = 0; k < 256; k++) {
                float wv = wp[k];
                #pragma unroll
                for (int q = 0; q < 8; q++) acc[q] += wv * o1[q * 256 + k];
            }
            float bb = fc2_b[tid];
            #pragma unroll
            for (int q = 0; q < 8; q++) o2[q * 128 + tid] = fmaxf(acc[q] + bb, 0.0f);
        }
        __syncthreads();

        if (tid < 8) {
            float sacc = 0.0f;
            for (int k = 0; k < 128; k++) sacc += fc3_W[k] * o2[tid * 128 + k];
            out[b0 + tid] = sacc + fc3_b[0];
        }
    }
}

// ---------------- launch -----------------------------------------------------
extern "C" void kernel_launch(void* const* d_in, const int* in_sizes, int n_in,
                              void* d_out, int out_size)
{
    const float* input  = (const float*)d_in[0];
    const float* l1_Wx  = (const float*)d_in[1];
    const float* l1_bx  = (const float*)d_in[2];
    const float* l1_Wh  = (const float*)d_in[3];
    const float* l1_bh  = (const float*)d_in[4];
    const float* l2_Wx  = (const float*)d_in[5];
    const float* l2_bx  = (const float*)d_in[6];
    const float* l2_Wh  = (const float*)d_in[7];
    const float* l2_bh  = (const float*)d_in[8];
    const float* fc1_W  = (const float*)d_in[9];
    const float* fc1_b  = (const float*)d_in[10];
    const float* fc2_W  = (const float*)d_in[11];
    const float* fc2_b  = (const float*)d_in[12];
    const float* fc3_W  = (const float*)d_in[13];
    const float* fc3_b  = (const float*)d_in[14];

    cudaFuncSetAttribute(lstm_all,
                         cudaFuncAttributeMaxDynamicSharedMemorySize, SMEM_DYN);

    lstm_all<<<NCTA, 256, SMEM_DYN>>>(input,
        l1_Wx, l1_bx, l1_Wh, l1_bh, l2_Wx, l2_bx, l2_Wh, l2_bh,
        fc1_W, fc1_b, fc2_W, fc2_b, fc3_W, fc3_b, (float*)d_out);
}

// round 11
// speedup vs baseline: 7.2664x; 1.0772x over previous
#include <cuda_runtime.h>
#include <cuda_fp16.h>
#include <math.h>
#include <stdint.h>

#define B_   256
#define T_   512
#define IN_  19
#define H_   512
#define KT1  9         // layer-1 chunks: 1 input + 8 hidden
#define KT2  16        // layer-2 chunks: 8 h1 + 8 h2
#define IMG  8192      // 64x64 fp16 swizzled image bytes (64 rows x 128B)
#define NCTA 128
#define ABUF  8192                  // one A chunk
#define APIPE (3 * ABUF)            // 24 KB A pipeline
#define B1OFF APIPE                 // 9 x 8KB resident layer-1 weights
#define B2OFF (B1OFF + KT1 * IMG)   // 16 x 8KB resident layer-2 weights
#define SMEM_DYN (B2OFF + KT2 * IMG)   // 229376 B = 224 KB

// ---------------- static device scratch (no allocs allowed) ----------------
__device__ __align__(16) unsigned char g_Bim1[32][KT1][IMG];   // [jb][chunk]
__device__ __align__(16) unsigned char g_Bim2[32][KT2][IMG];
__device__ __align__(16) unsigned char g_Ain[T_][4][IMG];      // [t][mh]
__device__ __align__(16) unsigned char g_h1im[2][4][8][IMG];   // [slot][mh][jchunk]
__device__ __align__(16) unsigned char g_h2im[2][4][8][IMG];
__device__ float g_bias1[4 * H_], g_bias2[4 * H_];
__device__ float g_h2fin[B_][H_];
__device__ volatile unsigned g_count;      // global barrier (monotonic gen)
__device__ volatile unsigned g_gen;
__device__ volatile unsigned g_cnt4[4];    // per-mh barriers
__device__ volatile unsigned g_gen4[4];

// ---------------- helpers ---------------------------------------------------
__device__ __forceinline__ uint32_t swz_(uint32_t o) { return o ^ ((o >> 3) & 0x70); }

__device__ __forceinline__ __half2 tanh2_(__half2 x) {
    __half2 y;
    asm("tanh.approx.f16x2 %0, %1;" : "=r"(*(uint32_t*)&y) : "r"(*(const uint32_t*)&x));
    return y;
}
__device__ __forceinline__ __half2 sigm2_(__half2 x) {
    const __half2 hhalf = __float2half2_rn(0.5f);
    return __hfma2(tanh2_(__hmul2(x, hhalf)), hhalf, hhalf);
}

__device__ __forceinline__ uint32_t smem_u32_(const void* p) {
    uint32_t a;
    asm("{ .reg .u64 t; cvta.to.shared.u64 t, %1; cvt.u32.u64 %0, t; }" : "=r"(a) : "l"(p));
    return a;
}
__device__ __forceinline__ void ldsm4_(uint32_t* r, uint32_t a) {
    asm volatile("ldmatrix.sync.aligned.m8n8.x4.shared.b16 {%0,%1,%2,%3}, [%4];"
        : "=r"(r[0]), "=r"(r[1]), "=r"(r[2]), "=r"(r[3]) : "r"(a));
}
__device__ __forceinline__ void mma_(float* d, const uint32_t* a, const uint32_t* b) {
    asm volatile("mma.sync.aligned.m16n8k16.row.col.f32.f16.f16.f32 "
        "{%0,%1,%2,%3}, {%4,%5,%6,%7}, {%8,%9}, {%0,%1,%2,%3};"
        : "+f"(d[0]), "+f"(d[1]), "+f"(d[2]), "+f"(d[3])
        : "r"(a[0]), "r"(a[1]), "r"(a[2]), "r"(a[3]), "r"(b[0]), "r"(b[1]));
}
__device__ __forceinline__ void cpa_(uint32_t sa, const void* ga) {
    asm volatile("cp.async.cg.shared.global [%0], [%1], 16;" :: "r"(sa), "l"(ga));
}
__device__ __forceinline__ void pk8_(const float* v, uint32_t* out4) {
    #pragma unroll
    for (int q = 0; q < 4; q++) {
        unsigned short h0 = __half_as_ushort(__float2half_rn(v[2 * q]));
        unsigned short h1 = __half_as_ushort(__float2half_rn(v[2 * q + 1]));
        out4[q] = (uint32_t)h0 | ((uint32_t)h1 << 16);
    }
}

// ---------------- barriers (monotonic gen, self-resetting count) -------------
__device__ __forceinline__ void bar_any_(volatile unsigned* cnt, volatile unsigned* gen,
                                         unsigned n) {
    __syncthreads();
    if (threadIdx.x == 0) {
        __threadfence();
        unsigned g = *gen;
        if (atomicAdd((unsigned*)cnt, 1u) == n - 1u) {
            *cnt = 0;
            __threadfence();
            *gen = g + 1u;
        } else {
            while (*gen == g) { }
        }
        __threadfence();
    }
    __syncthreads();
}

// ---------------- A-chunk issue (8KB, whole CTA) -----------------------------
__device__ __forceinline__ void issueA_(uint32_t abuf, const uint4* src, int tid)
{
    cpa_(abuf + (uint32_t)tid * 16,          src + tid);
    cpa_(abuf + (uint32_t)(tid + 256) * 16,  src + tid + 256);
    asm volatile("cp.async.commit_group;" ::: "memory");
}

// ---------------- one chunk of MMA (A stream + resident B) -------------------
__device__ __forceinline__ void compute_chunk_(uint32_t abuf, uint32_t bimg,
                                               float acc[8][4], int l, int w)
{
    const uint32_t arow  = (uint32_t)(w * 16 + (l & 15));
    const uint32_t abyte = (uint32_t)(((l >> 4) & 1) * 16);
    const uint32_t brow0 = (uint32_t)(((l >> 4) & 1) * 8 + (l & 7));
    const uint32_t bbyte = (uint32_t)(((l >> 3) & 1) * 16);

    #pragma unroll
    for (int ks = 0; ks < 4; ks++) {
        uint32_t a4[4];
        ldsm4_(a4, abuf + swz_(arow * 128 + (uint32_t)ks * 32 + abyte));
        #pragma unroll
        for (int tp = 0; tp < 4; tp++) {
            uint32_t b4[4];
            ldsm4_(b4, bimg + swz_(((uint32_t)tp * 16 + brow0) * 128 + (uint32_t)ks * 32 + bbyte));
            mma_(acc[2 * tp],     a4, b4);
            mma_(acc[2 * tp + 1], a4, b4 + 2);
        }
    }
}

// ---------------- fused LSTM cell epilogue (f16x2 MUFU path) -----------------
__device__ __forceinline__ void epilogue_(float acc[8][4], float* cst, const float* sb,
    int layer, int t, int mh, int jb, int w, int l, bool lastw)
{
    unsigned char* hb0 = (layer ? g_h2im : g_h1im)[(t + 1) & 1][mh][jb >> 2];

    #pragma unroll
    for (int a = 0; a < 2; a++) {
        #pragma unroll
        for (int rh = 0; rh < 2; rh++) {
            int row = 16 * w + (l >> 2) + rh * 8;
            int jj0 = 8 * a + 2 * (l & 3);
            float pi0 = acc[a][rh * 2 + 0]     + sb[jj0];
            float pi1 = acc[a][rh * 2 + 1]     + sb[jj0 + 1];
            float pf0 = acc[a + 2][rh * 2 + 0] + sb[16 + jj0];
            float pf1 = acc[a + 2][rh * 2 + 1] + sb[16 + jj0 + 1];
            float pg0 = acc[a + 4][rh * 2 + 0] + sb[32 + jj0];
            float pg1 = acc[a + 4][rh * 2 + 1] + sb[32 + jj0 + 1];
            float po0 = acc[a + 6][rh * 2 + 0] + sb[48 + jj0];
            float po1 = acc[a + 6][rh * 2 + 1] + sb[48 + jj0 + 1];

            __half2 si2 = sigm2_(__floats2half2_rn(pi0, pi1));
            __half2 sf2 = sigm2_(__floats2half2_rn(pf0, pf1));
            __half2 tg2 = tanh2_(__floats2half2_rn(pg0, pg1));
            __half2 so2 = sigm2_(__floats2half2_rn(po0, po1));

            float2 si = __half22float2(si2);
            float2 sf = __half22float2(sf2);
            float2 tg = __half22float2(tg2);

            int ci = a * 4 + rh * 2;
            float c0 = sf.x * cst[ci]     + si.x * tg.x;
            float c1 = sf.y * cst[ci + 1] + si.y * tg.y;
            cst[ci] = c0;
            cst[ci + 1] = c1;

            __half2 tc2 = tanh2_(__floats2half2_rn(c0, c1));
            __half2 h2v = __hmul2(so2, tc2);

            uint32_t off = swz_((uint32_t)(row * 128 + ((jb & 3) * 16 + jj0) * 2));
            *(uint32_t*)(hb0 + off) = *(const uint32_t*)&h2v;
            if (lastw) {
                float2 hf = __half22float2(h2v);
                g_h2fin[mh * 64 + row][jb * 16 + jj0]     = hf.x;
                g_h2fin[mh * 64 + row][jb * 16 + jj0 + 1] = hf.y;
            }
        }
    }
}

// ---------------- THE kernel ------------------------------------------------
// 128 CTAs x 256 threads, 1/SM (224KB smem). CTA (mh, jb) holds ALL its
// weights resident in smem; per interval only A streams (17 x 8KB):
// [in(s), h1(slot s&1) x8 (shared by both layers), h2(slot (s-1)&1) x8].
// Warps 0-3 = layer 1 (chunks 0..8), warps 4-7 = layer 2 (chunks 1..16).
// Per-mh 32-CTA barriers; one global barrier before the FC head.
__global__ void __launch_bounds__(256, 1) lstm_all(
    const float* __restrict__ input,
    const float* __restrict__ l1_Wx, const float* __restrict__ l1_bx,
    const float* __restrict__ l1_Wh, const float* __restrict__ l1_bh,
    const float* __restrict__ l2_Wx, const float* __restrict__ l2_bx,
    const float* __restrict__ l2_Wh, const float* __restrict__ l2_bh,
    const float* __restrict__ fc1_W, const float* __restrict__ fc1_b,
    const float* __restrict__ fc2_W, const float* __restrict__ fc2_b,
    const float* __restrict__ fc3_W, const float* __restrict__ fc3_b,
    float* __restrict__ out)
{
    extern __shared__ unsigned char dsm[];
    __shared__ float s_bias[2][64];

    const int tid = threadIdx.x;
    const int g  = tid >> 7;          // 0: layer-1 warps, 1: layer-2 warps
    const int gt = tid & 127;
    const int l  = gt & 31;
    const int w  = gt >> 5;
    const int mh = blockIdx.x >> 5;   // 0..3
    const int jb = blockIdx.x & 31;   // 0..31
    const uint32_t bufu = smem_u32_(dsm);

    // ================= prep phase (distributed across grid) =================
    {
        const int gi = blockIdx.x * 256 + tid;
        const int gs = NCTA * 256;

        for (int i = gi; i < 4 * H_; i += gs) {
            g_bias1[i] = l1_bx[i] + l1_bh[i];
            g_bias2[i] = l2_bx[i] + l2_bh[i];
        }
        {
            const int n16 = (4 * 8 * IMG) / 16;
            uint4 z = make_uint4(0, 0, 0, 0);
            uint4* p1 = (uint4*)&g_h1im[0][0][0][0];
            uint4* p2 = (uint4*)&g_h2im[0][0][0][0];
            for (int i = gi; i < n16; i += gs) { p1[i] = z; p2[i] = z; }
        }
        for (int e = gi; e < 32 * KT1 * 64 * 8; e += gs) {
            int k8 = e & 7, nrow = (e >> 3) & 63, c = (e >> 9) % KT1, jbx = (e >> 9) / KT1;
            int R = (nrow >> 4) * H_ + jbx * 16 + (nrow & 15);
            float v[8];
            #pragma unroll
            for (int q = 0; q < 8; q++) {
                int k = k8 * 8 + q;
                v[q] = (c == 0) ? ((k < IN_) ? l1_Wx[R * IN_ + k] : 0.0f)
                                : l1_Wh[R * H_ + (c - 1) * 64 + k];
            }
            uint32_t u4[4];
            pk8_(v, u4);
            *(uint4*)&g_Bim1[jbx][c][swz_((uint32_t)(nrow * 128 + k8 * 16))] =
                make_uint4(u4[0], u4[1], u4[2], u4[3]);
        }
        for (int e = gi; e < 32 * KT2 * 64 * 8; e += gs) {
            int k8 = e & 7, nrow = (e >> 3) & 63, c = (e >> 9) & 15, jbx = e >> 13;
            int R = (nrow >> 4) * H_ + jbx * 16 + (nrow & 15);
            float v[8];
            #pragma unroll
            for (int q = 0; q < 8; q++)
                v[q] = (c < 8) ? l2_Wx[R * H_ + c * 64 + k8 * 8 + q]
                               : l2_Wh[R * H_ + (c - 8) * 64 + k8 * 8 + q];
            uint32_t u4[4];
            pk8_(v, u4);
            *(uint4*)&g_Bim2[jbx][c][swz_((uint32_t)(nrow * 128 + k8 * 16))] =
                make_uint4(u4[0], u4[1], u4[2], u4[3]);
        }
        for (int e = gi; e < T_ * 4 * 64 * 8; e += gs) {
            int k8 = e & 7, r = (e >> 3) & 63, mhh = (e >> 9) & 3, t = e >> 11;
            int b = mhh * 64 + r;
            float v[8];
            #pragma unroll
            for (int q = 0; q < 8; q++) {
                int k = k8 * 8 + q;
                v[q] = (k < IN_) ? input[(size_t)b * (T_ * IN_) + t * IN_ + k] : 0.0f;
            }
            uint32_t u4[4];
            pk8_(v, u4);
            *(uint4*)&g_Ain[t][mhh][swz_((uint32_t)(r * 128 + k8 * 16))] =
                make_uint4(u4[0], u4[1], u4[2], u4[3]);
        }
    }
    bar_any_(&g_count, &g_gen, NCTA);   // prep visible everywhere

    // ---- load resident weights into smem (once per launch) ----
    {
        for (int img = 0; img < KT1 + KT2; img++) {
            const uint4* src = (img < KT1) ? (const uint4*)g_Bim1[jb][img]
                                           : (const uint4*)g_Bim2[jb][img - KT1];
            uint32_t dst = bufu + B1OFF + (uint32_t)img * IMG;
            cpa_(dst + (uint32_t)tid * 16,         src + tid);
            cpa_(dst + (uint32_t)(tid + 256) * 16, src + tid + 256);
        }
        asm volatile("cp.async.commit_group;" ::: "memory");
        asm volatile("cp.async.wait_group 0;" ::: "memory");
    }
    if (tid < 128) {
        int layer = tid >> 6, i = tid & 63;
        const float* bsrc = layer ? g_bias2 : g_bias1;
        s_bias[layer][i] = bsrc[(i >> 4) * H_ + jb * 16 + (i & 15)];
    }
    __syncthreads();

    // ================= persistent recurrence =================
    float cst[8];
    #pragma unroll
    for (int i = 0; i < 8; i++) cst[i] = 0.0f;   // g0: c1, g1: c2

    for (int s = 0; s <= T_; s++) {
        const bool hasL1 = (s < T_), hasL2 = (s >= 1);
        const int c0 = hasL1 ? 0 : 1;
        const int c1 = hasL2 ? 17 : 9;

        // A-chunk source for stream index i
        auto asrc = [&](int i) -> const uint4* {
            if (i == 0)      return (const uint4*)g_Ain[s][mh];
            else if (i < 9)  return (const uint4*)g_h1im[s & 1][mh][i - 1];
            else             return (const uint4*)g_h2im[(s - 1) & 1][mh][i - 9];
        };

        // prologue: issue first two chunks
        issueA_(bufu + (uint32_t)(c0 % 3) * ABUF,       asrc(c0), tid);
        issueA_(bufu + (uint32_t)((c0 + 1) % 3) * ABUF, asrc(c0 + 1), tid);

        float acc[8][4];
        for (int i = c0; i < c1; i++) {
            if (i < c1 - 1) asm volatile("cp.async.wait_group 1;" ::: "memory");
            else            asm volatile("cp.async.wait_group 0;" ::: "memory");
            __syncthreads();

            if (i + 2 < c1)
                issueA_(bufu + (uint32_t)((i + 2) % 3) * ABUF, asrc(i + 2), tid);

            const uint32_t abuf = bufu + (uint32_t)(i % 3) * ABUF;

            if (g == 0) {
                if (hasL1 && i < 9) {
                    if (i == c0) {
                        #pragma unroll
                        for (int nt = 0; nt < 8; nt++)
                            #pragma unroll
                            for (int r = 0; r < 4; r++) acc[nt][r] = 0.0f;
                    }
                    compute_chunk_(abuf, bufu + B1OFF + (uint32_t)i * IMG, acc, l, w);
                    if (i == 8)
                        epilogue_(acc, cst, s_bias[0], 0, s, mh, jb, w, l, false);
                }
            } else {
                if (hasL2 && i >= 1) {
                    if (i == 1) {
                        #pragma unroll
                        for (int nt = 0; nt < 8; nt++)
                            #pragma unroll
                            for (int r = 0; r < 4; r++) acc[nt][r] = 0.0f;
                    }
                    compute_chunk_(abuf, bufu + B2OFF + (uint32_t)(i - 1) * IMG, acc, l, w);
                    if (i == 16)
                        epilogue_(acc, cst, s_bias[1], 1, s - 1, mh, jb, w, l, (s - 1) == T_ - 1);
                }
            }
        }
        bar_any_(&g_cnt4[mh], &g_gen4[mh], 32);   // mh-scoped step barrier
    }

    bar_any_(&g_count, &g_gen, NCTA);   // all mh groups done -> head

    // ================= FC head (blocks 0..31, 8 batches each) ================
    if (blockIdx.x < 32) {
        float* hv = (float*)dsm;             // [8][512]
        float* o1 = hv + 8 * 512;            // [8][256]
        float* o2 = o1 + 8 * 256;            // [8][128]
        const int b0 = blockIdx.x * 8;

        for (int i = tid; i < 8 * 512; i += 256)
            hv[i] = g_h2fin[b0 + (i >> 9)][i & 511];
        __syncthreads();

        {
            float acc[8] = {};
            const float* wp = &fc1_W[tid * 512];
            for (int k = 0; k < 512; k++) {
                float wv = wp[k];
                #pragma unroll
                for (int q = 0; q < 8; q++) acc[q] += wv * hv[q * 512 + k];
            }
            float bb = fc1_b[tid];
            #pragma unroll
            for (int q = 0; q < 8; q++) o1[q * 256 + tid] = fmaxf(acc[q] + bb, 0.0f);
        }
        __syncthreads();

        if (tid < 128) {
            float acc[8] = {};
            const float* wp = &fc2_W[tid * 256];
            for (int k = 0; k < 256; k++) {
                float wv = wp[k];
                #pragma unroll
                for (int q = 0; q < 8; q++) acc[q] += wv * o1[q * 256 + k];
            }
            float bb = fc2_b[tid];
            #pragma unroll
            for (int q = 0; q < 8; q++) o2[q * 128 + tid] = fmaxf(acc[q] + bb, 0.0f);
        }
        __syncthreads();

        if (tid < 8) {
            float sacc = 0.0f;
            for (int k = 0; k < 128; k++) sacc += fc3_W[k] * o2[tid * 128 + k];
            out[b0 + tid] = sacc + fc3_b[0];
        }
    }
}

// ---------------- launch -----------------------------------------------------
extern "C" void kernel_launch(void* const* d_in, const int* in_sizes, int n_in,
                              void* d_out, int out_size)
{
    const float* input  = (const float*)d_in[0];
    const float* l1_Wx  = (const float*)d_in[1];
    const float* l1_bx  = (const float*)d_in[2];
    const float* l1_Wh  = (const float*)d_in[3];
    const float* l1_bh  = (const float*)d_in[4];
    const float* l2_Wx  = (const float*)d_in[5];
    const float* l2_bx  = (const float*)d_in[6];
    const float* l2_Wh  = (const float*)d_in[7];
    const float* l2_bh  = (const float*)d_in[8];
    const float* fc1_W  = (const float*)d_in[9];
    const float* fc1_b  = (const float*)d_in[10];
    const float* fc2_W  = (const float*)d_in[11];
    const float* fc2_b  = (const float*)d_in[12];
    const float* fc3_W  = (const float*)d_in[13];
    const float* fc3_b  = (const float*)d_in[14];

    cudaFuncSetAttribute(lstm_all,
                         cudaFuncAttributeMaxDynamicSharedMemorySize, SMEM_DYN);

    lstm_all<<<NCTA, 256, SMEM_DYN>>>(input,
        l1_Wx, l1_bx, l1_Wh, l1_bh, l2_Wx, l2_bx, l2_Wh, l2_bh,
        fc1_W, fc1_b, fc2_W, fc2_b, fc3_W, fc3_b, (float*)d_out);
}